// round 4
// baseline (speedup 1.0000x reference)
#include <cuda_runtime.h>

#define NN 50000
#define NE 1600000
#define D  128
#define OD 64
#define NL 3

// ---------------- device scratch ----------------
__device__ float g_h[NN * D];          // node features (output of each layer)
__device__ float g_x[NN * D];          // MLP hidden (pre-BN)
__device__ float g_stats[NL][2 * D];   // per-layer, per-channel sum & sumsq

// CSR (built per call, reused across 3 layers)
__device__ int g_cnt[NN];
__device__ int g_cur[NN];
__device__ int g_off[NN + 1];
__device__ int g_csrc[NE];

// ---------------- CSR build ----------------
__global__ void csr_zero_kernel() {
    int i = blockIdx.x * blockDim.x + threadIdx.x;
    if (i < NN) g_cnt[i] = 0;
    if (i == 0) g_off[0] = 0;
    if (i < NL * 2 * D) ((float*)g_stats)[i] = 0.f;
}

__global__ void csr_hist_kernel(const int* __restrict__ dst) {
    int e = blockIdx.x * blockDim.x + threadIdx.x;   // grid sized exactly NE
    atomicAdd(&g_cnt[__ldg(dst + e)], 1);
}

__global__ void csr_scan_kernel() {
    __shared__ int sh[1024];
    __shared__ int sbase;
    int tid = threadIdx.x;
    if (tid == 0) sbase = 0;
    __syncthreads();
    for (int chunk = 0; chunk < NN; chunk += 1024) {
        int i = chunk + tid;
        int v = (i < NN) ? g_cnt[i] : 0;
        sh[tid] = v;
        __syncthreads();
#pragma unroll
        for (int off = 1; off < 1024; off <<= 1) {
            int t = (tid >= off) ? sh[tid - off] : 0;
            __syncthreads();
            sh[tid] += t;
            __syncthreads();
        }
        int incl = sh[tid];
        int base = sbase;
        __syncthreads();
        if (tid == 1023) sbase = base + incl;
        if (i < NN) {
            g_off[i + 1] = base + incl;
            g_cur[i]     = base + incl - v;
        }
        __syncthreads();
    }
}

__global__ void csr_fill_kernel(const int* __restrict__ src,
                                const int* __restrict__ dst) {
    int e = blockIdx.x * blockDim.x + threadIdx.x;
    int d = __ldg(dst + e);
    int p = atomicAdd(&g_cur[d], 1);
    g_csrc[p] = __ldg(src + e);
}

// ---------------- GEMM1 fused with gather ----------------
// x = ((1+eps)h + sum_nbr h) @ W1 + b1, plus BN partial stats.
// BM=64, BN=128, 256 threads, 8x4 per-thread tile.
// Phase 1: CSR-gather the full 64x128 A tile into smem (transposed).
// Phase 2: 8 K-chunks of FFMA from smem, B double-buffered from global.
__global__ void __launch_bounds__(256) gemm1_fused_kernel(
        const float* __restrict__ nf,
        const float* __restrict__ W1,
        const float* __restrict__ b1,
        const float* __restrict__ eps,
        int layer) {
    __shared__ float As[D][68];        // As[k][m], 64 rows of A transposed
    __shared__ float Bs[2][16][128];

    const float* __restrict__ h = (layer == 0) ? nf : (const float*)g_h;

    int tid = threadIdx.x;
    int m0 = blockIdx.x * 64;
    const float* W = W1 + (size_t)layer * D * D;

    // ---- issue B chunk 0 loads early (latency hidden behind gather) ----
    const float4* Wv0 = (const float4*)W;
    float4 pb0 = Wv0[tid];
    float4 pb1 = Wv0[tid + 256];

    // ---- Phase 1: gather A tile ----
    {
        int lm = tid >> 2;            // row in tile 0..63
        int lq = tid & 3;             // column quarter: cols lq*32 .. lq*32+31
        int node = m0 + lm;
        float4 a[8];
        if (node < NN) {
            float oe = 1.0f + __ldg(eps + layer);
            const float4* hr = (const float4*)(h + (size_t)node * D + lq * 32);
#pragma unroll
            for (int j = 0; j < 8; j++) {
                float4 v = hr[j];
                a[j].x = oe * v.x; a[j].y = oe * v.y;
                a[j].z = oe * v.z; a[j].w = oe * v.w;
            }
            int beg = g_off[node];
            int end = g_off[node + 1];
            int i = beg;
            for (; i + 1 < end; i += 2) {
                int s0 = __ldg(g_csrc + i);
                int s1 = __ldg(g_csrc + i + 1);
                const float4* r0 = (const float4*)(h + (size_t)s0 * D + lq * 32);
                const float4* r1 = (const float4*)(h + (size_t)s1 * D + lq * 32);
#pragma unroll
                for (int j = 0; j < 8; j++) {
                    float4 v0 = r0[j];
                    float4 v1 = r1[j];
                    a[j].x += v0.x + v1.x;
                    a[j].y += v0.y + v1.y;
                    a[j].z += v0.z + v1.z;
                    a[j].w += v0.w + v1.w;
                }
            }
            if (i < end) {
                int s0 = __ldg(g_csrc + i);
                const float4* r0 = (const float4*)(h + (size_t)s0 * D + lq * 32);
#pragma unroll
                for (int j = 0; j < 8; j++) {
                    float4 v0 = r0[j];
                    a[j].x += v0.x; a[j].y += v0.y;
                    a[j].z += v0.z; a[j].w += v0.w;
                }
            }
        } else {
#pragma unroll
            for (int j = 0; j < 8; j++) a[j] = make_float4(0.f, 0.f, 0.f, 0.f);
        }
        // store transposed into As[k][m]
#pragma unroll
        for (int j = 0; j < 8; j++) {
            int k = lq * 32 + j * 4;
            As[k + 0][lm] = a[j].x;
            As[k + 1][lm] = a[j].y;
            As[k + 2][lm] = a[j].z;
            As[k + 3][lm] = a[j].w;
        }
        // stage B chunk 0
        float4* Bv = (float4*)&Bs[0][0][0];
        Bv[tid] = pb0; Bv[tid + 256] = pb1;
    }
    __syncthreads();

    // ---- Phase 2: GEMM from smem A ----
    int tn = tid & 31;
    int tm = tid >> 5;

    float acc[8][4];
#pragma unroll
    for (int r = 0; r < 8; r++)
#pragma unroll
        for (int c = 0; c < 4; c++) acc[r][c] = 0.f;

#pragma unroll
    for (int kk = 0; kk < 8; kk++) {
        const int cur = kk & 1;
        float4 nb0, nb1;
        if (kk < 7) {
            const float4* Wv = (const float4*)(W + (kk + 1) * 16 * D);
            nb0 = Wv[tid]; nb1 = Wv[tid + 256];
        }
#pragma unroll
        for (int k = 0; k < 16; k++) {
            float4 b = *(const float4*)(&Bs[cur][k][tn * 4]);
            float4 a0 = *(const float4*)(&As[kk * 16 + k][tm * 8]);
            float4 a1 = *(const float4*)(&As[kk * 16 + k][tm * 8 + 4]);
            float av[8] = {a0.x, a0.y, a0.z, a0.w, a1.x, a1.y, a1.z, a1.w};
#pragma unroll
            for (int r = 0; r < 8; r++) {
                acc[r][0] = fmaf(av[r], b.x, acc[r][0]);
                acc[r][1] = fmaf(av[r], b.y, acc[r][1]);
                acc[r][2] = fmaf(av[r], b.z, acc[r][2]);
                acc[r][3] = fmaf(av[r], b.w, acc[r][3]);
            }
        }
        if (kk < 7) {
            const int nxt = cur ^ 1;
            float4* Bv = (float4*)&Bs[nxt][0][0];
            Bv[tid] = nb0; Bv[tid + 256] = nb1;
            __syncthreads();
        }
    }

    // ---- epilogue: bias, store x, BN partial stats ----
    float4 bb = *(const float4*)(b1 + (size_t)layer * D + tn * 4);
    float s[4] = {0.f, 0.f, 0.f, 0.f}, q[4] = {0.f, 0.f, 0.f, 0.f};
#pragma unroll
    for (int r = 0; r < 8; r++) {
        int gm = m0 + tm * 8 + r;
        if (gm < NN) {
            float4 v;
            v.x = acc[r][0] + bb.x;
            v.y = acc[r][1] + bb.y;
            v.z = acc[r][2] + bb.z;
            v.w = acc[r][3] + bb.w;
            *(float4*)(g_x + (size_t)gm * D + tn * 4) = v;
            s[0] += v.x; s[1] += v.y; s[2] += v.z; s[3] += v.w;
            q[0] += v.x * v.x; q[1] += v.y * v.y;
            q[2] += v.z * v.z; q[3] += v.w * v.w;
        }
    }
    __syncthreads();
    float* Red = &Bs[0][0][0];  // reused as [2][8][128]
#pragma unroll
    for (int c = 0; c < 4; c++) {
        Red[(0 * 8 + tm) * 128 + tn * 4 + c] = s[c];
        Red[(1 * 8 + tm) * 128 + tn * 4 + c] = q[c];
    }
    __syncthreads();
    if (tm < 2) {
#pragma unroll
        for (int c = 0; c < 4; c++) {
            float t = 0.f;
#pragma unroll
            for (int r = 0; r < 8; r++) t += Red[(tm * 8 + r) * 128 + tn * 4 + c];
            atomicAdd(&g_stats[layer][tm * D + tn * 4 + c], t);
        }
    }
}

// ---------------- GEMM2 (pipelined, BN folded in): h = relu( relu(BN(x)) @ W2 + b2 ) ----------------
__global__ void __launch_bounds__(256) gemm2_kernel(const float* __restrict__ W2,
                                                    const float* __restrict__ b2,
                                                    const float* __restrict__ gamma,
                                                    const float* __restrict__ beta,
                                                    int layer) {
    __shared__ float Bs[2][16][128];
    __shared__ float As[2][16][68];
    __shared__ float s_sc[128], s_sh[128];

    int tid = threadIdx.x;
    int tn = tid & 31;
    int tm = tid >> 5;
    int m0 = blockIdx.x * 64;
    const float* W = W2 + (size_t)layer * D * D;

    // compute BN scale/shift from completed grid-wide stats
    if (tid < 128) {
        float inv = 1.0f / (float)NN;
        float mu = g_stats[layer][tid] * inv;
        float var = g_stats[layer][D + tid] * inv - mu * mu;
        float rs = rsqrtf(var + 1e-5f);
        float sc = rs * __ldg(gamma + (size_t)layer * D + tid);
        s_sc[tid] = sc;
        s_sh[tid] = __ldg(beta + (size_t)layer * D + tid) - mu * sc;
    }

    float acc[8][4];
#pragma unroll
    for (int r = 0; r < 8; r++)
#pragma unroll
        for (int c = 0; c < 4; c++) acc[r][c] = 0.f;

    int lm = tid >> 2;
    int lk = (tid & 3) * 4;
    int gm_ld = m0 + lm;

    // prologue: chunk 0 with BN+ReLU applied to A
    {
        float4 xv = make_float4(0.f, 0.f, 0.f, 0.f);
        if (gm_ld < NN) xv = *(const float4*)(g_x + (size_t)gm_ld * D + lk);
        const float4* Wv = (const float4*)W;
        float4 b0 = Wv[tid], b1v = Wv[tid + 256];
        __syncthreads();   // s_sc/s_sh ready
        float4 a;
        a.x = fmaxf(fmaf(xv.x, s_sc[lk + 0], s_sh[lk + 0]), 0.f);
        a.y = fmaxf(fmaf(xv.y, s_sc[lk + 1], s_sh[lk + 1]), 0.f);
        a.z = fmaxf(fmaf(xv.z, s_sc[lk + 2], s_sh[lk + 2]), 0.f);
        a.w = fmaxf(fmaf(xv.w, s_sc[lk + 3], s_sh[lk + 3]), 0.f);
        if (gm_ld >= NN) a = make_float4(0.f, 0.f, 0.f, 0.f);
        As[0][lk + 0][lm] = a.x; As[0][lk + 1][lm] = a.y;
        As[0][lk + 2][lm] = a.z; As[0][lk + 3][lm] = a.w;
        float4* Bv = (float4*)&Bs[0][0][0];
        Bv[tid] = b0; Bv[tid + 256] = b1v;
    }
    __syncthreads();

#pragma unroll
    for (int kk = 0; kk < 8; kk++) {
        const int cur = kk & 1;
        float4 na, nb0, nb1;
        if (kk < 7) {
            int kc = (kk + 1) * 16;
            na = make_float4(0.f, 0.f, 0.f, 0.f);
            if (gm_ld < NN) {
                const float4 xv = *(const float4*)(g_x + (size_t)gm_ld * D + kc + lk);
                na.x = fmaxf(fmaf(xv.x, s_sc[kc + lk + 0], s_sh[kc + lk + 0]), 0.f);
                na.y = fmaxf(fmaf(xv.y, s_sc[kc + lk + 1], s_sh[kc + lk + 1]), 0.f);
                na.z = fmaxf(fmaf(xv.z, s_sc[kc + lk + 2], s_sh[kc + lk + 2]), 0.f);
                na.w = fmaxf(fmaf(xv.w, s_sc[kc + lk + 3], s_sh[kc + lk + 3]), 0.f);
            }
            const float4* Wv = (const float4*)(W + kc * D);
            nb0 = Wv[tid]; nb1 = Wv[tid + 256];
        }
#pragma unroll
        for (int k = 0; k < 16; k++) {
            float4 b = *(const float4*)(&Bs[cur][k][tn * 4]);
            float4 a0 = *(const float4*)(&As[cur][k][tm * 8]);
            float4 a1 = *(const float4*)(&As[cur][k][tm * 8 + 4]);
            float av[8] = {a0.x, a0.y, a0.z, a0.w, a1.x, a1.y, a1.z, a1.w};
#pragma unroll
            for (int r = 0; r < 8; r++) {
                acc[r][0] = fmaf(av[r], b.x, acc[r][0]);
                acc[r][1] = fmaf(av[r], b.y, acc[r][1]);
                acc[r][2] = fmaf(av[r], b.z, acc[r][2]);
                acc[r][3] = fmaf(av[r], b.w, acc[r][3]);
            }
        }
        if (kk < 7) {
            const int nxt = cur ^ 1;
            As[nxt][lk + 0][lm] = na.x; As[nxt][lk + 1][lm] = na.y;
            As[nxt][lk + 2][lm] = na.z; As[nxt][lk + 3][lm] = na.w;
            float4* Bv = (float4*)&Bs[nxt][0][0];
            Bv[tid] = nb0; Bv[tid + 256] = nb1;
            __syncthreads();
        }
    }

    float4 bb = *(const float4*)(b2 + (size_t)layer * D + tn * 4);
#pragma unroll
    for (int r = 0; r < 8; r++) {
        int gm = m0 + tm * 8 + r;
        if (gm < NN) {
            float4 v;
            v.x = fmaxf(acc[r][0] + bb.x, 0.f);
            v.y = fmaxf(acc[r][1] + bb.y, 0.f);
            v.z = fmaxf(acc[r][2] + bb.z, 0.f);
            v.w = fmaxf(acc[r][3] + bb.w, 0.f);
            *(float4*)(g_h + (size_t)gm * D + tn * 4) = v;
        }
    }
}

// ---------------- GEMM3 (final): out = h @ Wout + bout ----------------
__global__ void __launch_bounds__(256) gemm3_kernel(const float* __restrict__ Wout,
                                                    const float* __restrict__ bout,
                                                    float* __restrict__ out) {
    __shared__ float Bs[16][64];
    __shared__ float As[16][68];

    int tid = threadIdx.x;
    int tn = tid & 15;
    int tm = tid >> 4;
    int m0 = blockIdx.x * 64;

    float acc[4][4];
#pragma unroll
    for (int r = 0; r < 4; r++)
#pragma unroll
        for (int c = 0; c < 4; c++) acc[r][c] = 0.f;

    int lm = tid >> 2;
    int lk = (tid & 3) * 4;
    int gm_ld = m0 + lm;

    for (int kk = 0; kk < D; kk += 16) {
        {
            const float4* Wv = (const float4*)(Wout + kk * OD);
            float4* Bv = (float4*)&Bs[0][0];
            Bv[tid] = Wv[tid];
        }
        {
            float4 a = make_float4(0.f, 0.f, 0.f, 0.f);
            if (gm_ld < NN) {
                a = *(const float4*)(g_h + (size_t)gm_ld * D + kk + lk);
            }
            As[lk + 0][lm] = a.x;
            As[lk + 1][lm] = a.y;
            As[lk + 2][lm] = a.z;
            As[lk + 3][lm] = a.w;
        }
        __syncthreads();
#pragma unroll
        for (int k = 0; k < 16; k++) {
            float4 b = *(const float4*)(&Bs[k][tn * 4]);
            float4 a = *(const float4*)(&As[k][tm * 4]);
            float av[4] = {a.x, a.y, a.z, a.w};
#pragma unroll
            for (int r = 0; r < 4; r++) {
                acc[r][0] = fmaf(av[r], b.x, acc[r][0]);
                acc[r][1] = fmaf(av[r], b.y, acc[r][1]);
                acc[r][2] = fmaf(av[r], b.z, acc[r][2]);
                acc[r][3] = fmaf(av[r], b.w, acc[r][3]);
            }
        }
        __syncthreads();
    }

    float4 bb = *(const float4*)(bout + tn * 4);
#pragma unroll
    for (int r = 0; r < 4; r++) {
        int gm = m0 + tm * 4 + r;
        if (gm < NN) {
            float4 v;
            v.x = acc[r][0] + bb.x;
            v.y = acc[r][1] + bb.y;
            v.z = acc[r][2] + bb.z;
            v.w = acc[r][3] + bb.w;
            *(float4*)(out + (size_t)gm * OD + tn * 4) = v;
        }
    }
}

// ---------------- launch ----------------
extern "C" void kernel_launch(void* const* d_in, const int* in_sizes, int n_in,
                              void* d_out, int out_size) {
    const float* node_feat = (const float*)d_in[0];
    const int*   src       = (const int*)d_in[1];
    const int*   dst       = (const int*)d_in[2];
    const float* W1        = (const float*)d_in[3];
    const float* b1        = (const float*)d_in[4];
    const float* gamma     = (const float*)d_in[5];
    const float* beta      = (const float*)d_in[6];
    const float* W2        = (const float*)d_in[7];
    const float* b2        = (const float*)d_in[8];
    const float* eps       = (const float*)d_in[9];
    const float* Wout      = (const float*)d_in[10];
    const float* bout      = (const float*)d_in[11];
    float* out = (float*)d_out;

    const int gemm_grid = (NN + 63) / 64;   // 782
    const int edge_grid = NE / 256;         // 6250 (exact)
    const int node_grid = (NN + 255) / 256; // 196

    // CSR build (once per call, reused by all 3 layers)
    csr_zero_kernel<<<node_grid, 256>>>();
    csr_hist_kernel<<<edge_grid, 256>>>(dst);
    csr_scan_kernel<<<1, 1024>>>();
    csr_fill_kernel<<<edge_grid, 256>>>(src, dst);

    for (int l = 0; l < NL; l++) {
        gemm1_fused_kernel<<<gemm_grid, 256>>>(node_feat, W1, b1, eps, l);
        gemm2_kernel<<<gemm_grid, 256>>>(W2, b2, gamma, beta, l);
    }
    gemm3_kernel<<<gemm_grid, 256>>>(Wout, bout, out);
}

// round 5
// speedup vs baseline: 1.7020x; 1.7020x over previous
#include <cuda_runtime.h>

#define NN 50000
#define NE 1600000
#define D  128
#define OD 64
#define NL 3

// ---------------- device scratch ----------------
__device__ float g_h[NN * D];          // node features (output of each layer)
__device__ float g_x[NN * D];          // MLP hidden (pre-BN)
__device__ float g_xin[NN * D];        // (1+eps)*h + agg   (GEMM1 input)
__device__ float g_stats[NL][2 * D];   // per-layer, per-channel sum & sumsq

// CSR (built per call, reused across 3 layers)
__device__ int g_cnt[NN];
__device__ int g_cur[NN];
__device__ int g_off[NN + 1];
__device__ int g_csrc[NE];

// ---------------- CSR build ----------------
__global__ void csr_zero_kernel() {
    int i = blockIdx.x * blockDim.x + threadIdx.x;
    if (i < NN) g_cnt[i] = 0;
    if (i == 0) g_off[0] = 0;
    if (i < NL * 2 * D) ((float*)g_stats)[i] = 0.f;
}

// 4 edges per thread (int4 load) -> 4 outstanding atomics, latency hidden
__global__ void csr_hist_kernel(const int* __restrict__ dst) {
    int i = blockIdx.x * blockDim.x + threadIdx.x;   // int4 index
    if (i >= NE / 4) return;
    int4 d = __ldg((const int4*)dst + i);
    atomicAdd(&g_cnt[d.x], 1);
    atomicAdd(&g_cnt[d.y], 1);
    atomicAdd(&g_cnt[d.z], 1);
    atomicAdd(&g_cnt[d.w], 1);
}

__global__ void csr_scan_kernel() {
    __shared__ int sh[1024];
    __shared__ int sbase;
    int tid = threadIdx.x;
    if (tid == 0) sbase = 0;
    __syncthreads();
    for (int chunk = 0; chunk < NN; chunk += 1024) {
        int i = chunk + tid;
        int v = (i < NN) ? g_cnt[i] : 0;
        sh[tid] = v;
        __syncthreads();
#pragma unroll
        for (int off = 1; off < 1024; off <<= 1) {
            int t = (tid >= off) ? sh[tid - off] : 0;
            __syncthreads();
            sh[tid] += t;
            __syncthreads();
        }
        int incl = sh[tid];
        int base = sbase;
        __syncthreads();
        if (tid == 1023) sbase = base + incl;
        if (i < NN) {
            g_off[i + 1] = base + incl;
            g_cur[i]     = base + incl - v;
        }
        __syncthreads();
    }
}

// 4 edges per thread (int4 loads)
__global__ void csr_fill_kernel(const int* __restrict__ src,
                                const int* __restrict__ dst) {
    int i = blockIdx.x * blockDim.x + threadIdx.x;   // int4 index
    if (i >= NE / 4) return;
    int4 s = __ldg((const int4*)src + i);
    int4 d = __ldg((const int4*)dst + i);
    int p0 = atomicAdd(&g_cur[d.x], 1);
    int p1 = atomicAdd(&g_cur[d.y], 1);
    int p2 = atomicAdd(&g_cur[d.z], 1);
    int p3 = atomicAdd(&g_cur[d.w], 1);
    g_csrc[p0] = s.x;
    g_csrc[p1] = s.y;
    g_csrc[p2] = s.z;
    g_csrc[p3] = s.w;
}

// ---------------- gather: xin[d] = (1+eps)*h[d] + sum_{s in N(d)} h[s] ----------------
// warp-per-node: all 32 lanes read one contiguous 512B row per neighbor.
__global__ void __launch_bounds__(256) gather_kernel(const float* __restrict__ nf,
                                                     const float* __restrict__ eps,
                                                     int layer) {
    const float* __restrict__ h = (layer == 0) ? nf : (const float*)g_h;

    int node = blockIdx.x * 8 + (threadIdx.x >> 5);
    if (node >= NN) return;
    int lane = threadIdx.x & 31;
    float oe = 1.0f + __ldg(eps + layer);

    int beg = g_off[node];
    int end = g_off[node + 1];

    const float4 hv = *(const float4*)(h + (size_t)node * D + lane * 4);
    float4 acc;
    acc.x = oe * hv.x; acc.y = oe * hv.y; acc.z = oe * hv.z; acc.w = oe * hv.w;

    int i = beg;
    for (; i + 3 < end; i += 4) {
        int s0 = __ldg(g_csrc + i);
        int s1 = __ldg(g_csrc + i + 1);
        int s2 = __ldg(g_csrc + i + 2);
        int s3 = __ldg(g_csrc + i + 3);
        float4 v0 = *(const float4*)(h + (size_t)s0 * D + lane * 4);
        float4 v1 = *(const float4*)(h + (size_t)s1 * D + lane * 4);
        float4 v2 = *(const float4*)(h + (size_t)s2 * D + lane * 4);
        float4 v3 = *(const float4*)(h + (size_t)s3 * D + lane * 4);
        acc.x += v0.x + v1.x + v2.x + v3.x;
        acc.y += v0.y + v1.y + v2.y + v3.y;
        acc.z += v0.z + v1.z + v2.z + v3.z;
        acc.w += v0.w + v1.w + v2.w + v3.w;
    }
    for (; i < end; i++) {
        int s = __ldg(g_csrc + i);
        float4 v = *(const float4*)(h + (size_t)s * D + lane * 4);
        acc.x += v.x; acc.y += v.y; acc.z += v.z; acc.w += v.w;
    }
    *(float4*)(g_xin + (size_t)node * D + lane * 4) = acc;
}

// ---------------- GEMM1 (pipelined): x = xin @ W1 + b1, + BN stats ----------------
// BM=64, BN=128, BK=16, 256 threads, 8x4 per-thread tile, double-buffered smem.
__global__ void __launch_bounds__(256) gemm1_kernel(const float* __restrict__ W1,
                                                    const float* __restrict__ b1,
                                                    int layer) {
    __shared__ float Bs[2][16][128];
    __shared__ float As[2][16][68];

    int tid = threadIdx.x;
    int tn = tid & 31;
    int tm = tid >> 5;
    int m0 = blockIdx.x * 64;
    const float* W = W1 + (size_t)layer * D * D;

    float acc[8][4];
#pragma unroll
    for (int r = 0; r < 8; r++)
#pragma unroll
        for (int c = 0; c < 4; c++) acc[r][c] = 0.f;

    int lm = tid >> 2;
    int lk = (tid & 3) * 4;
    int gm_ld = m0 + lm;

    // prologue: chunk 0
    {
        float4 a = make_float4(0.f, 0.f, 0.f, 0.f);
        if (gm_ld < NN) a = *(const float4*)(g_xin + (size_t)gm_ld * D + lk);
        const float4* Wv = (const float4*)W;
        float4 b0 = Wv[tid], b1v = Wv[tid + 256];
        As[0][lk + 0][lm] = a.x; As[0][lk + 1][lm] = a.y;
        As[0][lk + 2][lm] = a.z; As[0][lk + 3][lm] = a.w;
        float4* Bv = (float4*)&Bs[0][0][0];
        Bv[tid] = b0; Bv[tid + 256] = b1v;
    }
    __syncthreads();

#pragma unroll
    for (int kk = 0; kk < 8; kk++) {
        const int cur = kk & 1;
        float4 na, nb0, nb1;
        if (kk < 7) {
            int kc = (kk + 1) * 16;
            na = make_float4(0.f, 0.f, 0.f, 0.f);
            if (gm_ld < NN) na = *(const float4*)(g_xin + (size_t)gm_ld * D + kc + lk);
            const float4* Wv = (const float4*)(W + kc * D);
            nb0 = Wv[tid]; nb1 = Wv[tid + 256];
        }
#pragma unroll
        for (int k = 0; k < 16; k++) {
            float4 b = *(const float4*)(&Bs[cur][k][tn * 4]);
            float4 a0 = *(const float4*)(&As[cur][k][tm * 8]);
            float4 a1 = *(const float4*)(&As[cur][k][tm * 8 + 4]);
            float av[8] = {a0.x, a0.y, a0.z, a0.w, a1.x, a1.y, a1.z, a1.w};
#pragma unroll
            for (int r = 0; r < 8; r++) {
                acc[r][0] = fmaf(av[r], b.x, acc[r][0]);
                acc[r][1] = fmaf(av[r], b.y, acc[r][1]);
                acc[r][2] = fmaf(av[r], b.z, acc[r][2]);
                acc[r][3] = fmaf(av[r], b.w, acc[r][3]);
            }
        }
        if (kk < 7) {
            const int nxt = cur ^ 1;
            As[nxt][lk + 0][lm] = na.x; As[nxt][lk + 1][lm] = na.y;
            As[nxt][lk + 2][lm] = na.z; As[nxt][lk + 3][lm] = na.w;
            float4* Bv = (float4*)&Bs[nxt][0][0];
            Bv[tid] = nb0; Bv[tid + 256] = nb1;
            __syncthreads();
        }
    }

    // epilogue: bias, store x, BN partial stats (reuse Bs[0] as reduction buffer)
    float4 bb = *(const float4*)(b1 + (size_t)layer * D + tn * 4);
    float s[4] = {0.f, 0.f, 0.f, 0.f}, q[4] = {0.f, 0.f, 0.f, 0.f};
#pragma unroll
    for (int r = 0; r < 8; r++) {
        int gm = m0 + tm * 8 + r;
        if (gm < NN) {
            float4 v;
            v.x = acc[r][0] + bb.x;
            v.y = acc[r][1] + bb.y;
            v.z = acc[r][2] + bb.z;
            v.w = acc[r][3] + bb.w;
            *(float4*)(g_x + (size_t)gm * D + tn * 4) = v;
            s[0] += v.x; s[1] += v.y; s[2] += v.z; s[3] += v.w;
            q[0] += v.x * v.x; q[1] += v.y * v.y;
            q[2] += v.z * v.z; q[3] += v.w * v.w;
        }
    }
    __syncthreads();
    float* Red = &Bs[0][0][0];  // reused as [2][8][128]
#pragma unroll
    for (int c = 0; c < 4; c++) {
        Red[(0 * 8 + tm) * 128 + tn * 4 + c] = s[c];
        Red[(1 * 8 + tm) * 128 + tn * 4 + c] = q[c];
    }
    __syncthreads();
    if (tm < 2) {
#pragma unroll
        for (int c = 0; c < 4; c++) {
            float t = 0.f;
#pragma unroll
            for (int r = 0; r < 8; r++) t += Red[(tm * 8 + r) * 128 + tn * 4 + c];
            atomicAdd(&g_stats[layer][tm * D + tn * 4 + c], t);
        }
    }
}

// ---------------- GEMM2 (pipelined, BN folded in): h = relu( relu(BN(x)) @ W2 + b2 ) ----------------
__global__ void __launch_bounds__(256) gemm2_kernel(const float* __restrict__ W2,
                                                    const float* __restrict__ b2,
                                                    const float* __restrict__ gamma,
                                                    const float* __restrict__ beta,
                                                    int layer) {
    __shared__ float Bs[2][16][128];
    __shared__ float As[2][16][68];
    __shared__ float s_sc[128], s_sh[128];

    int tid = threadIdx.x;
    int tn = tid & 31;
    int tm = tid >> 5;
    int m0 = blockIdx.x * 64;
    const float* W = W2 + (size_t)layer * D * D;

    // compute BN scale/shift from completed grid-wide stats
    if (tid < 128) {
        float inv = 1.0f / (float)NN;
        float mu = g_stats[layer][tid] * inv;
        float var = g_stats[layer][D + tid] * inv - mu * mu;
        float rs = rsqrtf(var + 1e-5f);
        float sc = rs * __ldg(gamma + (size_t)layer * D + tid);
        s_sc[tid] = sc;
        s_sh[tid] = __ldg(beta + (size_t)layer * D + tid) - mu * sc;
    }

    float acc[8][4];
#pragma unroll
    for (int r = 0; r < 8; r++)
#pragma unroll
        for (int c = 0; c < 4; c++) acc[r][c] = 0.f;

    int lm = tid >> 2;
    int lk = (tid & 3) * 4;
    int gm_ld = m0 + lm;

    // prologue: chunk 0 with BN+ReLU applied to A
    {
        float4 xv = make_float4(0.f, 0.f, 0.f, 0.f);
        if (gm_ld < NN) xv = *(const float4*)(g_x + (size_t)gm_ld * D + lk);
        const float4* Wv = (const float4*)W;
        float4 b0 = Wv[tid], b1v = Wv[tid + 256];
        __syncthreads();   // s_sc/s_sh ready
        float4 a;
        a.x = fmaxf(fmaf(xv.x, s_sc[lk + 0], s_sh[lk + 0]), 0.f);
        a.y = fmaxf(fmaf(xv.y, s_sc[lk + 1], s_sh[lk + 1]), 0.f);
        a.z = fmaxf(fmaf(xv.z, s_sc[lk + 2], s_sh[lk + 2]), 0.f);
        a.w = fmaxf(fmaf(xv.w, s_sc[lk + 3], s_sh[lk + 3]), 0.f);
        if (gm_ld >= NN) a = make_float4(0.f, 0.f, 0.f, 0.f);
        As[0][lk + 0][lm] = a.x; As[0][lk + 1][lm] = a.y;
        As[0][lk + 2][lm] = a.z; As[0][lk + 3][lm] = a.w;
        float4* Bv = (float4*)&Bs[0][0][0];
        Bv[tid] = b0; Bv[tid + 256] = b1v;
    }
    __syncthreads();

#pragma unroll
    for (int kk = 0; kk < 8; kk++) {
        const int cur = kk & 1;
        float4 na, nb0, nb1;
        if (kk < 7) {
            int kc = (kk + 1) * 16;
            na = make_float4(0.f, 0.f, 0.f, 0.f);
            if (gm_ld < NN) {
                const float4 xv = *(const float4*)(g_x + (size_t)gm_ld * D + kc + lk);
                na.x = fmaxf(fmaf(xv.x, s_sc[kc + lk + 0], s_sh[kc + lk + 0]), 0.f);
                na.y = fmaxf(fmaf(xv.y, s_sc[kc + lk + 1], s_sh[kc + lk + 1]), 0.f);
                na.z = fmaxf(fmaf(xv.z, s_sc[kc + lk + 2], s_sh[kc + lk + 2]), 0.f);
                na.w = fmaxf(fmaf(xv.w, s_sc[kc + lk + 3], s_sh[kc + lk + 3]), 0.f);
            }
            const float4* Wv = (const float4*)(W + kc * D);
            nb0 = Wv[tid]; nb1 = Wv[tid + 256];
        }
#pragma unroll
        for (int k = 0; k < 16; k++) {
            float4 b = *(const float4*)(&Bs[cur][k][tn * 4]);
            float4 a0 = *(const float4*)(&As[cur][k][tm * 8]);
            float4 a1 = *(const float4*)(&As[cur][k][tm * 8 + 4]);
            float av[8] = {a0.x, a0.y, a0.z, a0.w, a1.x, a1.y, a1.z, a1.w};
#pragma unroll
            for (int r = 0; r < 8; r++) {
                acc[r][0] = fmaf(av[r], b.x, acc[r][0]);
                acc[r][1] = fmaf(av[r], b.y, acc[r][1]);
                acc[r][2] = fmaf(av[r], b.z, acc[r][2]);
                acc[r][3] = fmaf(av[r], b.w, acc[r][3]);
            }
        }
        if (kk < 7) {
            const int nxt = cur ^ 1;
            As[nxt][lk + 0][lm] = na.x; As[nxt][lk + 1][lm] = na.y;
            As[nxt][lk + 2][lm] = na.z; As[nxt][lk + 3][lm] = na.w;
            float4* Bv = (float4*)&Bs[nxt][0][0];
            Bv[tid] = nb0; Bv[tid + 256] = nb1;
            __syncthreads();
        }
    }

    float4 bb = *(const float4*)(b2 + (size_t)layer * D + tn * 4);
#pragma unroll
    for (int r = 0; r < 8; r++) {
        int gm = m0 + tm * 8 + r;
        if (gm < NN) {
            float4 v;
            v.x = fmaxf(acc[r][0] + bb.x, 0.f);
            v.y = fmaxf(acc[r][1] + bb.y, 0.f);
            v.z = fmaxf(acc[r][2] + bb.z, 0.f);
            v.w = fmaxf(acc[r][3] + bb.w, 0.f);
            *(float4*)(g_h + (size_t)gm * D + tn * 4) = v;
        }
    }
}

// ---------------- GEMM3 (final): out = h @ Wout + bout ----------------
__global__ void __launch_bounds__(256) gemm3_kernel(const float* __restrict__ Wout,
                                                    const float* __restrict__ bout,
                                                    float* __restrict__ out) {
    __shared__ float Bs[16][64];
    __shared__ float As[16][68];

    int tid = threadIdx.x;
    int tn = tid & 15;
    int tm = tid >> 4;
    int m0 = blockIdx.x * 64;

    float acc[4][4];
#pragma unroll
    for (int r = 0; r < 4; r++)
#pragma unroll
        for (int c = 0; c < 4; c++) acc[r][c] = 0.f;

    int lm = tid >> 2;
    int lk = (tid & 3) * 4;
    int gm_ld = m0 + lm;

    for (int kk = 0; kk < D; kk += 16) {
        {
            const float4* Wv = (const float4*)(Wout + kk * OD);
            float4* Bv = (float4*)&Bs[0][0];
            Bv[tid] = Wv[tid];
        }
        {
            float4 a = make_float4(0.f, 0.f, 0.f, 0.f);
            if (gm_ld < NN) {
                a = *(const float4*)(g_h + (size_t)gm_ld * D + kk + lk);
            }
            As[lk + 0][lm] = a.x;
            As[lk + 1][lm] = a.y;
            As[lk + 2][lm] = a.z;
            As[lk + 3][lm] = a.w;
        }
        __syncthreads();
#pragma unroll
        for (int k = 0; k < 16; k++) {
            float4 b = *(const float4*)(&Bs[k][tn * 4]);
            float4 a = *(const float4*)(&As[k][tm * 4]);
            float av[4] = {a.x, a.y, a.z, a.w};
#pragma unroll
            for (int r = 0; r < 4; r++) {
                acc[r][0] = fmaf(av[r], b.x, acc[r][0]);
                acc[r][1] = fmaf(av[r], b.y, acc[r][1]);
                acc[r][2] = fmaf(av[r], b.z, acc[r][2]);
                acc[r][3] = fmaf(av[r], b.w, acc[r][3]);
            }
        }
        __syncthreads();
    }

    float4 bb = *(const float4*)(bout + tn * 4);
#pragma unroll
    for (int r = 0; r < 4; r++) {
        int gm = m0 + tm * 4 + r;
        if (gm < NN) {
            float4 v;
            v.x = acc[r][0] + bb.x;
            v.y = acc[r][1] + bb.y;
            v.z = acc[r][2] + bb.z;
            v.w = acc[r][3] + bb.w;
            *(float4*)(out + (size_t)gm * OD + tn * 4) = v;
        }
    }
}

// ---------------- launch ----------------
extern "C" void kernel_launch(void* const* d_in, const int* in_sizes, int n_in,
                              void* d_out, int out_size) {
    const float* node_feat = (const float*)d_in[0];
    const int*   src       = (const int*)d_in[1];
    const int*   dst       = (const int*)d_in[2];
    const float* W1        = (const float*)d_in[3];
    const float* b1        = (const float*)d_in[4];
    const float* gamma     = (const float*)d_in[5];
    const float* beta      = (const float*)d_in[6];
    const float* W2        = (const float*)d_in[7];
    const float* b2        = (const float*)d_in[8];
    const float* eps       = (const float*)d_in[9];
    const float* Wout      = (const float*)d_in[10];
    const float* bout      = (const float*)d_in[11];
    float* out = (float*)d_out;

    const int gemm_grid  = (NN + 63) / 64;          // 782
    const int edge4_grid = (NE / 4 + 255) / 256;    // 1563
    const int node_grid  = (NN + 255) / 256;        // 196
    const int gath_grid  = (NN + 7) / 8;            // 6250

    // CSR build (once per call, reused by all 3 layers)
    csr_zero_kernel<<<node_grid, 256>>>();
    csr_hist_kernel<<<edge4_grid, 256>>>(dst);
    csr_scan_kernel<<<1, 1024>>>();
    csr_fill_kernel<<<edge4_grid, 256>>>(src, dst);

    for (int l = 0; l < NL; l++) {
        gather_kernel<<<gath_grid, 256>>>(node_feat, eps, l);
        gemm1_kernel<<<gemm_grid, 256>>>(W1, b1, l);
        gemm2_kernel<<<gemm_grid, 256>>>(W2, b2, gamma, beta, l);
    }
    gemm3_kernel<<<gemm_grid, 256>>>(Wout, bout, out);
}

// round 7
// speedup vs baseline: 2.1107x; 1.2402x over previous
#include <cuda_runtime.h>
#include <cuda_bf16.h>

#define NN 50000
#define NE 1600000
#define D  128
#define OD 64
#define NL 3

// ---------------- device scratch ----------------
__device__ float g_h[NN * D];          // node features (fp32)
__device__ float g_x[NN * D];          // MLP hidden pre-BN (fp32)
__device__ float g_xin[NN * D];        // (1+eps)h + agg (fp32)
__device__ float g_stats[NL][2 * D];   // per-layer per-channel sum & sumsq

// Pre-split weights, laid out as the exact smem image:
// [layer][chunk(8)][hi/lo(2)][n(128)][kpair(8)]  (each uint = 2 bf16, low = even k)
__device__ unsigned g_w1p[NL][8][2][128][8];
__device__ unsigned g_w2p[NL][8][2][128][8];

// CSR
__device__ int g_cnt[NN];
__device__ int g_cur[NN];
__device__ int g_off[NN + 1];
__device__ int g_csrc[NE];

__device__ __forceinline__ unsigned pack_bf2(float a, float b) {
    __nv_bfloat162 t = __floats2bfloat162_rn(a, b);
    return *reinterpret_cast<unsigned*>(&t);
}
__device__ __forceinline__ float bf_hi(float x) {
    return __bfloat162float(__float2bfloat16_rn(x));
}

__device__ __forceinline__ void mma_bf16(float* d, const unsigned* a,
                                         unsigned b0, unsigned b1) {
    asm volatile(
        "mma.sync.aligned.m16n8k16.row.col.f32.bf16.bf16.f32 "
        "{%0,%1,%2,%3}, {%4,%5,%6,%7}, {%8,%9}, {%0,%1,%2,%3};"
        : "+f"(d[0]), "+f"(d[1]), "+f"(d[2]), "+f"(d[3])
        : "r"(a[0]), "r"(a[1]), "r"(a[2]), "r"(a[3]), "r"(b0), "r"(b1));
}

// ---------------- CSR build ----------------
__global__ void csr_zero_kernel() {
    int i = blockIdx.x * blockDim.x + threadIdx.x;
    if (i < NN) g_cnt[i] = 0;
    if (i == 0) g_off[0] = 0;
    if (i < NL * 2 * D) ((float*)g_stats)[i] = 0.f;
}

// Pre-split weights into hi/lo bf16 pairs in the smem-image layout.
// One thread per (layer, kpair, n): i = l*8192 + kp*128 + n  (n fastest -> coalesced)
__global__ void cvt_w_kernel(const float* __restrict__ W1,
                             const float* __restrict__ W2) {
    int i = blockIdx.x * blockDim.x + threadIdx.x;
    if (i >= NL * 64 * 128) return;
    int n = i & 127;
    int kp = (i >> 7) & 63;
    int l = i >> 13;
    int k0 = kp * 2;
    int chunk = k0 >> 4;
    int kpi = (k0 & 15) >> 1;

    {
        float w0 = __ldg(W1 + (size_t)l * D * D + k0 * D + n);
        float w1 = __ldg(W1 + (size_t)l * D * D + (k0 + 1) * D + n);
        float h0 = bf_hi(w0), h1 = bf_hi(w1);
        g_w1p[l][chunk][0][n][kpi] = pack_bf2(h0, h1);
        g_w1p[l][chunk][1][n][kpi] = pack_bf2(w0 - h0, w1 - h1);
    }
    {
        float w0 = __ldg(W2 + (size_t)l * D * D + k0 * D + n);
        float w1 = __ldg(W2 + (size_t)l * D * D + (k0 + 1) * D + n);
        float h0 = bf_hi(w0), h1 = bf_hi(w1);
        g_w2p[l][chunk][0][n][kpi] = pack_bf2(h0, h1);
        g_w2p[l][chunk][1][n][kpi] = pack_bf2(w0 - h0, w1 - h1);
    }
}

__global__ void csr_hist_kernel(const int* __restrict__ dst) {
    int i = blockIdx.x * blockDim.x + threadIdx.x;
    if (i >= NE / 4) return;
    int4 d = __ldg((const int4*)dst + i);
    atomicAdd(&g_cnt[d.x], 1);
    atomicAdd(&g_cnt[d.y], 1);
    atomicAdd(&g_cnt[d.z], 1);
    atomicAdd(&g_cnt[d.w], 1);
}

__global__ void csr_scan_kernel() {
    __shared__ int sh[1024];
    __shared__ int sbase;
    int tid = threadIdx.x;
    if (tid == 0) sbase = 0;
    __syncthreads();
    for (int chunk = 0; chunk < NN; chunk += 1024) {
        int i = chunk + tid;
        int v = (i < NN) ? g_cnt[i] : 0;
        sh[tid] = v;
        __syncthreads();
#pragma unroll
        for (int off = 1; off < 1024; off <<= 1) {
            int t = (tid >= off) ? sh[tid - off] : 0;
            __syncthreads();
            sh[tid] += t;
            __syncthreads();
        }
        int incl = sh[tid];
        int base = sbase;
        __syncthreads();
        if (tid == 1023) sbase = base + incl;
        if (i < NN) {
            g_off[i + 1] = base + incl;
            g_cur[i]     = base + incl - v;
        }
        __syncthreads();
    }
}

__global__ void csr_fill_kernel(const int* __restrict__ src,
                                const int* __restrict__ dst) {
    int i = blockIdx.x * blockDim.x + threadIdx.x;
    if (i >= NE / 4) return;
    int4 s = __ldg((const int4*)src + i);
    int4 d = __ldg((const int4*)dst + i);
    int p0 = atomicAdd(&g_cur[d.x], 1);
    int p1 = atomicAdd(&g_cur[d.y], 1);
    int p2 = atomicAdd(&g_cur[d.z], 1);
    int p3 = atomicAdd(&g_cur[d.w], 1);
    g_csrc[p0] = s.x;
    g_csrc[p1] = s.y;
    g_csrc[p2] = s.z;
    g_csrc[p3] = s.w;
}

// ---------------- gather: xin[d] = (1+eps)h[d] + sum_nbr h (fp32) ----------------
__global__ void __launch_bounds__(256) gather_kernel(const float* __restrict__ nf,
                                                     const float* __restrict__ eps,
                                                     int layer) {
    const float* __restrict__ h = (layer == 0) ? nf : (const float*)g_h;

    int node = blockIdx.x * 8 + (threadIdx.x >> 5);
    if (node >= NN) return;
    int lane = threadIdx.x & 31;
    float oe = 1.0f + __ldg(eps + layer);

    int beg = g_off[node];
    int end = g_off[node + 1];

    const float4 hv = *(const float4*)(h + (size_t)node * D + lane * 4);
    float4 acc;
    acc.x = oe * hv.x; acc.y = oe * hv.y; acc.z = oe * hv.z; acc.w = oe * hv.w;

    int i = beg;
    for (; i + 3 < end; i += 4) {
        int s0 = __ldg(g_csrc + i);
        int s1 = __ldg(g_csrc + i + 1);
        int s2 = __ldg(g_csrc + i + 2);
        int s3 = __ldg(g_csrc + i + 3);
        float4 v0 = *(const float4*)(h + (size_t)s0 * D + lane * 4);
        float4 v1 = *(const float4*)(h + (size_t)s1 * D + lane * 4);
        float4 v2 = *(const float4*)(h + (size_t)s2 * D + lane * 4);
        float4 v3 = *(const float4*)(h + (size_t)s3 * D + lane * 4);
        acc.x += v0.x + v1.x + v2.x + v3.x;
        acc.y += v0.y + v1.y + v2.y + v3.y;
        acc.z += v0.z + v1.z + v2.z + v3.z;
        acc.w += v0.w + v1.w + v2.w + v3.w;
    }
    for (; i < end; i++) {
        int s = __ldg(g_csrc + i);
        float4 v = *(const float4*)(h + (size_t)s * D + lane * 4);
        acc.x += v.x; acc.y += v.y; acc.z += v.z; acc.w += v.w;
    }
    *(float4*)(g_xin + (size_t)node * D + lane * 4) = acc;
}

// =====================================================================
// Split-bf16 tensor-core GEMM core (shared by gemm1/gemm2 bodies).
// BM=64, BN=128, K-chunk=16, 256 thr = 8 warps (4m x 2n), warp tile 16x64.
// smem images (uints, 2 bf16 each, low half = even k):
//   A_hi/A_lo: [64][8]   B_hi/B_lo: [128][8]
// Per chunk per warp: 8 n-tiles x 3 mma.m16n8k16 (hh, hl, lh).
// =====================================================================

struct SmemGemm {
    unsigned A[2][2][64 * 8];    // [buf][hi/lo][m*8 + kpair]
    unsigned B[2][2][128 * 8];   // [buf][hi/lo][n*8 + kpair]
};

// split 4 consecutive fp32 (k = lk..lk+3) into 2 hi-uints and 2 lo-uints
__device__ __forceinline__ void split4(float4 v, unsigned* hi, unsigned* lo) {
    float h0 = bf_hi(v.x), h1 = bf_hi(v.y), h2 = bf_hi(v.z), h3 = bf_hi(v.w);
    hi[0] = pack_bf2(h0, h1);
    hi[1] = pack_bf2(h2, h3);
    lo[0] = pack_bf2(v.x - h0, v.y - h1);
    lo[1] = pack_bf2(v.z - h2, v.w - h3);
}

// ---------------- GEMM1: x = xin @ W1 + b1, + BN stats ----------------
__global__ void __launch_bounds__(256) gemm1_tc_kernel(const float* __restrict__ b1,
                                                       int layer) {
    __shared__ SmemGemm sm;
    __shared__ float SredS[128], SredQ[128];

    int tid = threadIdx.x;
    int lane = tid & 31;
    int wid = tid >> 5;
    int wm = wid & 3;
    int wn = wid >> 2;
    int m0 = blockIdx.x * 64;

    if (tid < 128) { SredS[tid] = 0.f; SredQ[tid] = 0.f; }

    int lm = tid >> 2;              // A row 0..63
    int lq = (tid & 3);             // kpair group: kpairs 2lq, 2lq+1 (k = 4lq..4lq+3)
    int gm_ld = m0 + lm;
    const unsigned* Wc = &g_w1p[layer][0][0][0][0];   // [chunk][2][128][8]

    // prologue: chunk 0
    {
        float4 v = make_float4(0.f, 0.f, 0.f, 0.f);
        if (gm_ld < NN) v = *(const float4*)(g_xin + (size_t)gm_ld * D + lq * 4);
        unsigned hi[2], lo[2];
        split4(v, hi, lo);
        sm.A[0][0][lm * 8 + lq * 2] = hi[0];
        sm.A[0][0][lm * 8 + lq * 2 + 1] = hi[1];
        sm.A[0][1][lm * 8 + lq * 2] = lo[0];
        sm.A[0][1][lm * 8 + lq * 2 + 1] = lo[1];
        const uint4* Wg = (const uint4*)Wc;   // chunk0: hi 1024 uints, lo 1024 uints
        uint4 wh = Wg[tid], wl = Wg[tid + 256];
        ((uint4*)sm.B[0][0])[tid] = wh;
        ((uint4*)sm.B[0][1])[tid] = wl;
    }
    __syncthreads();

    float d[8][4];
#pragma unroll
    for (int nt = 0; nt < 8; nt++)
#pragma unroll
        for (int c = 0; c < 4; c++) d[nt][c] = 0.f;

    int kq = lane & 3;
    int gr = lane >> 2;
    int ca = wm * 16 + gr;          // A row for a0/a2

#pragma unroll
    for (int kk = 0; kk < 8; kk++) {
        const int cur = kk & 1;
        unsigned nah[2], nal[2];
        uint4 nwh, nwl;
        if (kk < 7) {
            float4 v = make_float4(0.f, 0.f, 0.f, 0.f);
            if (gm_ld < NN)
                v = *(const float4*)(g_xin + (size_t)gm_ld * D + (kk + 1) * 16 + lq * 4);
            split4(v, nah, nal);
            const uint4* Wg = (const uint4*)(Wc + (kk + 1) * 2048);
            nwh = Wg[tid]; nwl = Wg[tid + 256];
        }
        // fragments
        unsigned ah[4], al[4];
        ah[0] = sm.A[cur][0][ca * 8 + kq];
        ah[1] = sm.A[cur][0][(ca + 8) * 8 + kq];
        ah[2] = sm.A[cur][0][ca * 8 + kq + 4];
        ah[3] = sm.A[cur][0][(ca + 8) * 8 + kq + 4];
        al[0] = sm.A[cur][1][ca * 8 + kq];
        al[1] = sm.A[cur][1][(ca + 8) * 8 + kq];
        al[2] = sm.A[cur][1][ca * 8 + kq + 4];
        al[3] = sm.A[cur][1][(ca + 8) * 8 + kq + 4];
#pragma unroll
        for (int nt = 0; nt < 8; nt++) {
            int cb = wn * 64 + nt * 8 + gr;
            unsigned bh0 = sm.B[cur][0][cb * 8 + kq];
            unsigned bh1 = sm.B[cur][0][cb * 8 + kq + 4];
            unsigned bl0 = sm.B[cur][1][cb * 8 + kq];
            unsigned bl1 = sm.B[cur][1][cb * 8 + kq + 4];
            mma_bf16(d[nt], ah, bh0, bh1);
            mma_bf16(d[nt], ah, bl0, bl1);
            mma_bf16(d[nt], al, bh0, bh1);
        }
        if (kk < 7) {
            const int nxt = cur ^ 1;
            sm.A[nxt][0][lm * 8 + lq * 2] = nah[0];
            sm.A[nxt][0][lm * 8 + lq * 2 + 1] = nah[1];
            sm.A[nxt][1][lm * 8 + lq * 2] = nal[0];
            sm.A[nxt][1][lm * 8 + lq * 2 + 1] = nal[1];
            ((uint4*)sm.B[nxt][0])[tid] = nwh;
            ((uint4*)sm.B[nxt][1])[tid] = nwl;
            __syncthreads();
        }
    }

    // epilogue: bias, store x, BN stats
    int r0 = m0 + wm * 16 + gr;
    int r1 = r0 + 8;
    bool v0r = (r0 < NN), v1r = (r1 < NN);
#pragma unroll
    for (int nt = 0; nt < 8; nt++) {
        int c0 = wn * 64 + nt * 8 + 2 * kq;
        float bb0 = __ldg(b1 + (size_t)layer * D + c0);
        float bb1 = __ldg(b1 + (size_t)layer * D + c0 + 1);
        float x0 = d[nt][0] + bb0, x1 = d[nt][1] + bb1;
        float x2 = d[nt][2] + bb0, x3 = d[nt][3] + bb1;
        if (v0r) *(float2*)(g_x + (size_t)r0 * D + c0) = make_float2(x0, x1);
        if (v1r) *(float2*)(g_x + (size_t)r1 * D + c0) = make_float2(x2, x3);
        float sc0 = (v0r ? x0 : 0.f) + (v1r ? x2 : 0.f);
        float sc1 = (v0r ? x1 : 0.f) + (v1r ? x3 : 0.f);
        float qc0 = (v0r ? x0 * x0 : 0.f) + (v1r ? x2 * x2 : 0.f);
        float qc1 = (v0r ? x1 * x1 : 0.f) + (v1r ? x3 * x3 : 0.f);
#pragma unroll
        for (int o = 4; o <= 16; o <<= 1) {
            sc0 += __shfl_xor_sync(0xffffffffu, sc0, o);
            sc1 += __shfl_xor_sync(0xffffffffu, sc1, o);
            qc0 += __shfl_xor_sync(0xffffffffu, qc0, o);
            qc1 += __shfl_xor_sync(0xffffffffu, qc1, o);
        }
        if (gr == 0) {
            atomicAdd(&SredS[c0], sc0);
            atomicAdd(&SredS[c0 + 1], sc1);
            atomicAdd(&SredQ[c0], qc0);
            atomicAdd(&SredQ[c0 + 1], qc1);
        }
    }
    __syncthreads();
    if (tid < 128) {
        atomicAdd(&g_stats[layer][tid], SredS[tid]);
        atomicAdd(&g_stats[layer][D + tid], SredQ[tid]);
    }
}

// ---------------- GEMM2: h = relu( relu(BN(x)) @ W2 + b2 ) ----------------
__global__ void __launch_bounds__(256) gemm2_tc_kernel(const float* __restrict__ b2,
                                                       const float* __restrict__ gamma,
                                                       const float* __restrict__ beta,
                                                       int layer) {
    __shared__ SmemGemm sm;
    __shared__ float s_sc[128], s_sh[128];

    int tid = threadIdx.x;
    int lane = tid & 31;
    int wid = tid >> 5;
    int wm = wid & 3;
    int wn = wid >> 2;
    int m0 = blockIdx.x * 64;

    if (tid < 128) {
        float inv = 1.0f / (float)NN;
        float mu = g_stats[layer][tid] * inv;
        float var = g_stats[layer][D + tid] * inv - mu * mu;
        float rs = rsqrtf(var + 1e-5f);
        float sc = rs * __ldg(gamma + (size_t)layer * D + tid);
        s_sc[tid] = sc;
        s_sh[tid] = __ldg(beta + (size_t)layer * D + tid) - mu * sc;
    }
    __syncthreads();

    int lm = tid >> 2;
    int lq = (tid & 3);
    int gm_ld = m0 + lm;
    const unsigned* Wc = &g_w2p[layer][0][0][0][0];

    // prologue chunk 0: A = relu(BN(x)) split
    {
        float4 v = make_float4(0.f, 0.f, 0.f, 0.f);
        if (gm_ld < NN) {
            float4 xv = *(const float4*)(g_x + (size_t)gm_ld * D + lq * 4);
            int c = lq * 4;
            v.x = fmaxf(fmaf(xv.x, s_sc[c + 0], s_sh[c + 0]), 0.f);
            v.y = fmaxf(fmaf(xv.y, s_sc[c + 1], s_sh[c + 1]), 0.f);
            v.z = fmaxf(fmaf(xv.z, s_sc[c + 2], s_sh[c + 2]), 0.f);
            v.w = fmaxf(fmaf(xv.w, s_sc[c + 3], s_sh[c + 3]), 0.f);
        }
        unsigned hi[2], lo[2];
        split4(v, hi, lo);
        sm.A[0][0][lm * 8 + lq * 2] = hi[0];
        sm.A[0][0][lm * 8 + lq * 2 + 1] = hi[1];
        sm.A[0][1][lm * 8 + lq * 2] = lo[0];
        sm.A[0][1][lm * 8 + lq * 2 + 1] = lo[1];
        const uint4* Wg = (const uint4*)Wc;
        uint4 wh = Wg[tid], wl = Wg[tid + 256];
        ((uint4*)sm.B[0][0])[tid] = wh;
        ((uint4*)sm.B[0][1])[tid] = wl;
    }
    __syncthreads();

    float d[8][4];
#pragma unroll
    for (int nt = 0; nt < 8; nt++)
#pragma unroll
        for (int c = 0; c < 4; c++) d[nt][c] = 0.f;

    int kq = lane & 3;
    int gr = lane >> 2;
    int ca = wm * 16 + gr;

#pragma unroll
    for (int kk = 0; kk < 8; kk++) {
        const int cur = kk & 1;
        unsigned nah[2], nal[2];
        uint4 nwh, nwl;
        if (kk < 7) {
            float4 v = make_float4(0.f, 0.f, 0.f, 0.f);
            int kc = (kk + 1) * 16;
            if (gm_ld < NN) {
                float4 xv = *(const float4*)(g_x + (size_t)gm_ld * D + kc + lq * 4);
                int c = kc + lq * 4;
                v.x = fmaxf(fmaf(xv.x, s_sc[c + 0], s_sh[c + 0]), 0.f);
                v.y = fmaxf(fmaf(xv.y, s_sc[c + 1], s_sh[c + 1]), 0.f);
                v.z = fmaxf(fmaf(xv.z, s_sc[c + 2], s_sh[c + 2]), 0.f);
                v.w = fmaxf(fmaf(xv.w, s_sc[c + 3], s_sh[c + 3]), 0.f);
            }
            split4(v, nah, nal);
            const uint4* Wg = (const uint4*)(Wc + (kk + 1) * 2048);
            nwh = Wg[tid]; nwl = Wg[tid + 256];
        }
        unsigned ah[4], al[4];
        ah[0] = sm.A[cur][0][ca * 8 + kq];
        ah[1] = sm.A[cur][0][(ca + 8) * 8 + kq];
        ah[2] = sm.A[cur][0][ca * 8 + kq + 4];
        ah[3] = sm.A[cur][0][(ca + 8) * 8 + kq + 4];
        al[0] = sm.A[cur][1][ca * 8 + kq];
        al[1] = sm.A[cur][1][(ca + 8) * 8 + kq];
        al[2] = sm.A[cur][1][ca * 8 + kq + 4];
        al[3] = sm.A[cur][1][(ca + 8) * 8 + kq + 4];
#pragma unroll
        for (int nt = 0; nt < 8; nt++) {
            int cb = wn * 64 + nt * 8 + gr;
            unsigned bh0 = sm.B[cur][0][cb * 8 + kq];
            unsigned bh1 = sm.B[cur][0][cb * 8 + kq + 4];
            unsigned bl0 = sm.B[cur][1][cb * 8 + kq];
            unsigned bl1 = sm.B[cur][1][cb * 8 + kq + 4];
            mma_bf16(d[nt], ah, bh0, bh1);
            mma_bf16(d[nt], ah, bl0, bl1);
            mma_bf16(d[nt], al, bh0, bh1);
        }
        if (kk < 7) {
            const int nxt = cur ^ 1;
            sm.A[nxt][0][lm * 8 + lq * 2] = nah[0];
            sm.A[nxt][0][lm * 8 + lq * 2 + 1] = nah[1];
            sm.A[nxt][1][lm * 8 + lq * 2] = nal[0];
            sm.A[nxt][1][lm * 8 + lq * 2 + 1] = nal[1];
            ((uint4*)sm.B[nxt][0])[tid] = nwh;
            ((uint4*)sm.B[nxt][1])[tid] = nwl;
            __syncthreads();
        }
    }

    // epilogue: relu(d + b2) -> g_h
    int r0 = m0 + wm * 16 + gr;
    int r1 = r0 + 8;
#pragma unroll
    for (int nt = 0; nt < 8; nt++) {
        int c0 = wn * 64 + nt * 8 + 2 * kq;
        float bb0 = __ldg(b2 + (size_t)layer * D + c0);
        float bb1 = __ldg(b2 + (size_t)layer * D + c0 + 1);
        if (r0 < NN) {
            float2 v = make_float2(fmaxf(d[nt][0] + bb0, 0.f),
                                   fmaxf(d[nt][1] + bb1, 0.f));
            *(float2*)(g_h + (size_t)r0 * D + c0) = v;
        }
        if (r1 < NN) {
            float2 v = make_float2(fmaxf(d[nt][2] + bb0, 0.f),
                                   fmaxf(d[nt][3] + bb1, 0.f));
            *(float2*)(g_h + (size_t)r1 * D + c0) = v;
        }
    }
}

// ---------------- GEMM3 (final, FFMA fp32): out = h @ Wout + bout ----------------
__global__ void __launch_bounds__(256) gemm3_kernel(const float* __restrict__ Wout,
                                                    const float* __restrict__ bout,
                                                    float* __restrict__ out) {
    __shared__ float Bs[16][64];
    __shared__ float As[16][68];

    int tid = threadIdx.x;
    int tn = tid & 15;
    int tm = tid >> 4;
    int m0 = blockIdx.x * 64;

    float acc[4][4];
#pragma unroll
    for (int r = 0; r < 4; r++)
#pragma unroll
        for (int c = 0; c < 4; c++) acc[r][c] = 0.f;

    int lm = tid >> 2;
    int lk = (tid & 3) * 4;
    int gm_ld = m0 + lm;

    for (int kk = 0; kk < D; kk += 16) {
        {
            const float4* Wv = (const float4*)(Wout + kk * OD);
            float4* Bv = (float4*)&Bs[0][0];
            Bv[tid] = Wv[tid];
        }
        {
            float4 a = make_float4(0.f, 0.f, 0.f, 0.f);
            if (gm_ld < NN) {
                a = *(const float4*)(g_h + (size_t)gm_ld * D + kk + lk);
            }
            As[lk + 0][lm] = a.x;
            As[lk + 1][lm] = a.y;
            As[lk + 2][lm] = a.z;
            As[lk + 3][lm] = a.w;
        }
        __syncthreads();
#pragma unroll
        for (int k = 0; k < 16; k++) {
            float4 b = *(const float4*)(&Bs[k][tn * 4]);
            float4 a = *(const float4*)(&As[k][tm * 4]);
            float av[4] = {a.x, a.y, a.z, a.w};
#pragma unroll
            for (int r = 0; r < 4; r++) {
                acc[r][0] = fmaf(av[r], b.x, acc[r][0]);
                acc[r][1] = fmaf(av[r], b.y, acc[r][1]);
                acc[r][2] = fmaf(av[r], b.z, acc[r][2]);
                acc[r][3] = fmaf(av[r], b.w, acc[r][3]);
            }
        }
        __syncthreads();
    }

    float4 bb = *(const float4*)(bout + tn * 4);
#pragma unroll
    for (int r = 0; r < 4; r++) {
        int gm = m0 + tm * 4 + r;
        if (gm < NN) {
            float4 v;
            v.x = acc[r][0] + bb.x;
            v.y = acc[r][1] + bb.y;
            v.z = acc[r][2] + bb.z;
            v.w = acc[r][3] + bb.w;
            *(float4*)(out + (size_t)gm * OD + tn * 4) = v;
        }
    }
}

// ---------------- launch ----------------
extern "C" void kernel_launch(void* const* d_in, const int* in_sizes, int n_in,
                              void* d_out, int out_size) {
    const float* node_feat = (const float*)d_in[0];
    const int*   src       = (const int*)d_in[1];
    const int*   dst       = (const int*)d_in[2];
    const float* W1        = (const float*)d_in[3];
    const float* b1        = (const float*)d_in[4];
    const float* gamma     = (const float*)d_in[5];
    const float* beta      = (const float*)d_in[6];
    const float* W2        = (const float*)d_in[7];
    const float* b2        = (const float*)d_in[8];
    const float* eps       = (const float*)d_in[9];
    const float* Wout      = (const float*)d_in[10];
    const float* bout      = (const float*)d_in[11];
    float* out = (float*)d_out;

    const int gemm_grid  = (NN + 63) / 64;          // 782
    const int edge4_grid = (NE / 4 + 255) / 256;    // 1563
    const int node_grid  = (NN + 255) / 256;        // 196
    const int gath_grid  = (NN + 7) / 8;            // 6250
    const int cvtw_grid  = (NL * 64 * 128 + 255) / 256;

    csr_zero_kernel<<<node_grid, 256>>>();
    cvt_w_kernel<<<cvtw_grid, 256>>>(W1, W2);
    csr_hist_kernel<<<edge4_grid, 256>>>(dst);
    csr_scan_kernel<<<1, 1024>>>();
    csr_fill_kernel<<<edge4_grid, 256>>>(src, dst);

    for (int l = 0; l < NL; l++) {
        gather_kernel<<<gath_grid, 256>>>(node_feat, eps, l);
        gemm1_tc_kernel<<<gemm_grid, 256>>>(b1, l);
        gemm2_tc_kernel<<<gemm_grid, 256>>>(b2, gamma, beta, l);
    }
    gemm3_kernel<<<gemm_grid, 256>>>(Wout, bout, out);
}

// round 8
// speedup vs baseline: 2.4475x; 1.1595x over previous
#include <cuda_runtime.h>
#include <cuda_bf16.h>

#define NN 50000
#define NE 1600000
#define D  128
#define OD 64
#define NL 3
#define NBLK 196   // ceil(NN/256)

// ---------------- device scratch ----------------
__device__ float g_h[NN * D];          // node features (fp32)
__device__ float g_x[NN * D];          // MLP hidden pre-BN (fp32)
__device__ float g_xin[NN * D];        // (1+eps)h + agg (fp32)
__device__ float g_stats[NL][2 * D];   // per-layer per-channel sum & sumsq

// Pre-split weights, laid out as the exact smem image:
// [layer][chunk(8)][hi/lo(2)][n(128)][kpair(8)]  (each uint = 2 bf16, low = even k)
__device__ unsigned g_w1p[NL][8][2][128][8];
__device__ unsigned g_w2p[NL][8][2][128][8];

// CSR
__device__ int g_cnt[NN];
__device__ int g_cur[NN];
__device__ int g_off[NN + 1];
__device__ int g_csrc[NE];
__device__ int g_bsum[NBLK + 1];

__device__ __forceinline__ unsigned pack_bf2(float a, float b) {
    __nv_bfloat162 t = __floats2bfloat162_rn(a, b);
    return *reinterpret_cast<unsigned*>(&t);
}
__device__ __forceinline__ float bf_hi(float x) {
    return __bfloat162float(__float2bfloat16_rn(x));
}

__device__ __forceinline__ void mma_bf16(float* d, const unsigned* a,
                                         unsigned b0, unsigned b1) {
    asm volatile(
        "mma.sync.aligned.m16n8k16.row.col.f32.bf16.bf16.f32 "
        "{%0,%1,%2,%3}, {%4,%5,%6,%7}, {%8,%9}, {%0,%1,%2,%3};"
        : "+f"(d[0]), "+f"(d[1]), "+f"(d[2]), "+f"(d[3])
        : "r"(a[0]), "r"(a[1]), "r"(a[2]), "r"(a[3]), "r"(b0), "r"(b1));
}

// ---------------- CSR build ----------------
__global__ void csr_zero_kernel() {
    int i = blockIdx.x * blockDim.x + threadIdx.x;
    if (i < NN) g_cnt[i] = 0;
    if (i == 0) g_off[0] = 0;
    if (i < NL * 2 * D) ((float*)g_stats)[i] = 0.f;
}

// Pre-split weights into hi/lo bf16 pairs in the smem-image layout.
__global__ void cvt_w_kernel(const float* __restrict__ W1,
                             const float* __restrict__ W2) {
    int i = blockIdx.x * blockDim.x + threadIdx.x;
    if (i >= NL * 64 * 128) return;
    int n = i & 127;
    int kp = (i >> 7) & 63;
    int l = i >> 13;
    int k0 = kp * 2;
    int chunk = k0 >> 4;
    int kpi = (k0 & 15) >> 1;

    {
        float w0 = __ldg(W1 + (size_t)l * D * D + k0 * D + n);
        float w1 = __ldg(W1 + (size_t)l * D * D + (k0 + 1) * D + n);
        float h0 = bf_hi(w0), h1 = bf_hi(w1);
        g_w1p[l][chunk][0][n][kpi] = pack_bf2(h0, h1);
        g_w1p[l][chunk][1][n][kpi] = pack_bf2(w0 - h0, w1 - h1);
    }
    {
        float w0 = __ldg(W2 + (size_t)l * D * D + k0 * D + n);
        float w1 = __ldg(W2 + (size_t)l * D * D + (k0 + 1) * D + n);
        float h0 = bf_hi(w0), h1 = bf_hi(w1);
        g_w2p[l][chunk][0][n][kpi] = pack_bf2(h0, h1);
        g_w2p[l][chunk][1][n][kpi] = pack_bf2(w0 - h0, w1 - h1);
    }
}

__global__ void csr_hist_kernel(const int* __restrict__ dst) {
    int i = blockIdx.x * blockDim.x + threadIdx.x;
    if (i >= NE / 4) return;
    int4 d = __ldg((const int4*)dst + i);
    atomicAdd(&g_cnt[d.x], 1);
    atomicAdd(&g_cnt[d.y], 1);
    atomicAdd(&g_cnt[d.z], 1);
    atomicAdd(&g_cnt[d.w], 1);
}

// --- hierarchical scan: per-block inclusive scan + block sums ---
__global__ void scan1_kernel() {
    int b = blockIdx.x, tid = threadIdx.x;
    int i = b * 256 + tid;
    int v = (i < NN) ? g_cnt[i] : 0;
    int lane = tid & 31, w = tid >> 5;
    int x = v;
#pragma unroll
    for (int o = 1; o < 32; o <<= 1) {
        int t = __shfl_up_sync(0xffffffffu, x, o);
        if (lane >= o) x += t;
    }
    __shared__ int wsum[8];
    if (lane == 31) wsum[w] = x;
    __syncthreads();
    if (w == 0 && lane < 8) {
        int y = wsum[lane];
#pragma unroll
        for (int o = 1; o < 8; o <<= 1) {
            int t = __shfl_up_sync(0xffu, y, o);
            if (lane >= o) y += t;
        }
        wsum[lane] = y;
    }
    __syncthreads();
    int incl = x + (w > 0 ? wsum[w - 1] : 0);
    if (i < NN) {
        g_off[i + 1] = incl;        // local inclusive (base added in scan3)
        g_cur[i] = incl - v;        // local exclusive
    }
    if (tid == 255) g_bsum[b] = incl;
}

// exclusive scan of NBLK block sums (single block, 256 threads)
__global__ void scan2_kernel() {
    int tid = threadIdx.x;
    int lane = tid & 31, w = tid >> 5;
    int v = (tid < NBLK) ? g_bsum[tid] : 0;
    int x = v;
#pragma unroll
    for (int o = 1; o < 32; o <<= 1) {
        int t = __shfl_up_sync(0xffffffffu, x, o);
        if (lane >= o) x += t;
    }
    __shared__ int wsum[8];
    if (lane == 31) wsum[w] = x;
    __syncthreads();
    if (w == 0 && lane < 8) {
        int y = wsum[lane];
#pragma unroll
        for (int o = 1; o < 8; o <<= 1) {
            int t = __shfl_up_sync(0xffu, y, o);
            if (lane >= o) y += t;
        }
        wsum[lane] = y;
    }
    __syncthreads();
    int incl = x + (w > 0 ? wsum[w - 1] : 0);
    if (tid < NBLK) g_bsum[tid] = incl - v;   // exclusive base per block
}

__global__ void scan3_kernel() {
    int b = blockIdx.x;
    int i = b * 256 + threadIdx.x;
    if (i < NN) {
        int base = g_bsum[b];
        g_off[i + 1] += base;
        g_cur[i] += base;
    }
}

__global__ void csr_fill_kernel(const int* __restrict__ src,
                                const int* __restrict__ dst) {
    int i = blockIdx.x * blockDim.x + threadIdx.x;
    if (i >= NE / 4) return;
    int4 s = __ldg((const int4*)src + i);
    int4 d = __ldg((const int4*)dst + i);
    int p0 = atomicAdd(&g_cur[d.x], 1);
    int p1 = atomicAdd(&g_cur[d.y], 1);
    int p2 = atomicAdd(&g_cur[d.z], 1);
    int p3 = atomicAdd(&g_cur[d.w], 1);
    g_csrc[p0] = s.x;
    g_csrc[p1] = s.y;
    g_csrc[p2] = s.z;
    g_csrc[p3] = s.w;
}

// ---------------- gather: xin[d] = (1+eps)h[d] + sum_nbr h (fp32) ----------------
__global__ void __launch_bounds__(256) gather_kernel(const float* __restrict__ nf,
                                                     const float* __restrict__ eps,
                                                     int layer) {
    const float* __restrict__ h = (layer == 0) ? nf : (const float*)g_h;

    int node = blockIdx.x * 8 + (threadIdx.x >> 5);
    if (node >= NN) return;
    int lane = threadIdx.x & 31;
    float oe = 1.0f + __ldg(eps + layer);

    int beg = g_off[node];
    int end = g_off[node + 1];

    const float4 hv = *(const float4*)(h + (size_t)node * D + lane * 4);
    float4 acc;
    acc.x = oe * hv.x; acc.y = oe * hv.y; acc.z = oe * hv.z; acc.w = oe * hv.w;

    int i = beg;
    for (; i + 3 < end; i += 4) {
        int s0 = __ldg(g_csrc + i);
        int s1 = __ldg(g_csrc + i + 1);
        int s2 = __ldg(g_csrc + i + 2);
        int s3 = __ldg(g_csrc + i + 3);
        float4 v0 = *(const float4*)(h + (size_t)s0 * D + lane * 4);
        float4 v1 = *(const float4*)(h + (size_t)s1 * D + lane * 4);
        float4 v2 = *(const float4*)(h + (size_t)s2 * D + lane * 4);
        float4 v3 = *(const float4*)(h + (size_t)s3 * D + lane * 4);
        acc.x += v0.x + v1.x + v2.x + v3.x;
        acc.y += v0.y + v1.y + v2.y + v3.y;
        acc.z += v0.z + v1.z + v2.z + v3.z;
        acc.w += v0.w + v1.w + v2.w + v3.w;
    }
    for (; i < end; i++) {
        int s = __ldg(g_csrc + i);
        float4 v = *(const float4*)(h + (size_t)s * D + lane * 4);
        acc.x += v.x; acc.y += v.y; acc.z += v.z; acc.w += v.w;
    }
    *(float4*)(g_xin + (size_t)node * D + lane * 4) = acc;
}

// =====================================================================
// Split-bf16 tensor-core GEMM core.
// =====================================================================

struct SmemGemm {
    unsigned A[2][2][64 * 8];    // [buf][hi/lo][m*8 + kpair]
    unsigned B[2][2][128 * 8];   // [buf][hi/lo][n*8 + kpair]
};

__device__ __forceinline__ void split4(float4 v, unsigned* hi, unsigned* lo) {
    float h0 = bf_hi(v.x), h1 = bf_hi(v.y), h2 = bf_hi(v.z), h3 = bf_hi(v.w);
    hi[0] = pack_bf2(h0, h1);
    hi[1] = pack_bf2(h2, h3);
    lo[0] = pack_bf2(v.x - h0, v.y - h1);
    lo[1] = pack_bf2(v.z - h2, v.w - h3);
}

// ---------------- GEMM1: x = xin @ W1 + b1, + BN stats ----------------
__global__ void __launch_bounds__(256) gemm1_tc_kernel(const float* __restrict__ b1,
                                                       int layer) {
    __shared__ SmemGemm sm;
    __shared__ float SredS[128], SredQ[128];

    int tid = threadIdx.x;
    int lane = tid & 31;
    int wid = tid >> 5;
    int wm = wid & 3;
    int wn = wid >> 2;
    int m0 = blockIdx.x * 64;

    if (tid < 128) { SredS[tid] = 0.f; SredQ[tid] = 0.f; }

    int lm = tid >> 2;
    int lq = (tid & 3);
    int gm_ld = m0 + lm;
    const unsigned* Wc = &g_w1p[layer][0][0][0][0];

    // prologue: chunk 0
    {
        float4 v = make_float4(0.f, 0.f, 0.f, 0.f);
        if (gm_ld < NN) v = *(const float4*)(g_xin + (size_t)gm_ld * D + lq * 4);
        unsigned hi[2], lo[2];
        split4(v, hi, lo);
        sm.A[0][0][lm * 8 + lq * 2] = hi[0];
        sm.A[0][0][lm * 8 + lq * 2 + 1] = hi[1];
        sm.A[0][1][lm * 8 + lq * 2] = lo[0];
        sm.A[0][1][lm * 8 + lq * 2 + 1] = lo[1];
        const uint4* Wg = (const uint4*)Wc;
        uint4 wh = Wg[tid], wl = Wg[tid + 256];
        ((uint4*)sm.B[0][0])[tid] = wh;
        ((uint4*)sm.B[0][1])[tid] = wl;
    }
    __syncthreads();

    float d[8][4];
#pragma unroll
    for (int nt = 0; nt < 8; nt++)
#pragma unroll
        for (int c = 0; c < 4; c++) d[nt][c] = 0.f;

    int kq = lane & 3;
    int gr = lane >> 2;
    int ca = wm * 16 + gr;

#pragma unroll
    for (int kk = 0; kk < 8; kk++) {
        const int cur = kk & 1;
        unsigned nah[2], nal[2];
        uint4 nwh, nwl;
        if (kk < 7) {
            float4 v = make_float4(0.f, 0.f, 0.f, 0.f);
            if (gm_ld < NN)
                v = *(const float4*)(g_xin + (size_t)gm_ld * D + (kk + 1) * 16 + lq * 4);
            split4(v, nah, nal);
            const uint4* Wg = (const uint4*)(Wc + (kk + 1) * 2048);
            nwh = Wg[tid]; nwl = Wg[tid + 256];
        }
        unsigned ah[4], al[4];
        ah[0] = sm.A[cur][0][ca * 8 + kq];
        ah[1] = sm.A[cur][0][(ca + 8) * 8 + kq];
        ah[2] = sm.A[cur][0][ca * 8 + kq + 4];
        ah[3] = sm.A[cur][0][(ca + 8) * 8 + kq + 4];
        al[0] = sm.A[cur][1][ca * 8 + kq];
        al[1] = sm.A[cur][1][(ca + 8) * 8 + kq];
        al[2] = sm.A[cur][1][ca * 8 + kq + 4];
        al[3] = sm.A[cur][1][(ca + 8) * 8 + kq + 4];
#pragma unroll
        for (int nt = 0; nt < 8; nt++) {
            int cb = wn * 64 + nt * 8 + gr;
            unsigned bh0 = sm.B[cur][0][cb * 8 + kq];
            unsigned bh1 = sm.B[cur][0][cb * 8 + kq + 4];
            unsigned bl0 = sm.B[cur][1][cb * 8 + kq];
            unsigned bl1 = sm.B[cur][1][cb * 8 + kq + 4];
            mma_bf16(d[nt], ah, bh0, bh1);
            mma_bf16(d[nt], ah, bl0, bl1);
            mma_bf16(d[nt], al, bh0, bh1);
        }
        if (kk < 7) {
            const int nxt = cur ^ 1;
            sm.A[nxt][0][lm * 8 + lq * 2] = nah[0];
            sm.A[nxt][0][lm * 8 + lq * 2 + 1] = nah[1];
            sm.A[nxt][1][lm * 8 + lq * 2] = nal[0];
            sm.A[nxt][1][lm * 8 + lq * 2 + 1] = nal[1];
            ((uint4*)sm.B[nxt][0])[tid] = nwh;
            ((uint4*)sm.B[nxt][1])[tid] = nwl;
            __syncthreads();
        }
    }

    // epilogue: bias, store x, BN stats
    int r0 = m0 + wm * 16 + gr;
    int r1 = r0 + 8;
    bool v0r = (r0 < NN), v1r = (r1 < NN);
#pragma unroll
    for (int nt = 0; nt < 8; nt++) {
        int c0 = wn * 64 + nt * 8 + 2 * kq;
        float bb0 = __ldg(b1 + (size_t)layer * D + c0);
        float bb1 = __ldg(b1 + (size_t)layer * D + c0 + 1);
        float x0 = d[nt][0] + bb0, x1 = d[nt][1] + bb1;
        float x2 = d[nt][2] + bb0, x3 = d[nt][3] + bb1;
        if (v0r) *(float2*)(g_x + (size_t)r0 * D + c0) = make_float2(x0, x1);
        if (v1r) *(float2*)(g_x + (size_t)r1 * D + c0) = make_float2(x2, x3);
        float sc0 = (v0r ? x0 : 0.f) + (v1r ? x2 : 0.f);
        float sc1 = (v0r ? x1 : 0.f) + (v1r ? x3 : 0.f);
        float qc0 = (v0r ? x0 * x0 : 0.f) + (v1r ? x2 * x2 : 0.f);
        float qc1 = (v0r ? x1 * x1 : 0.f) + (v1r ? x3 * x3 : 0.f);
#pragma unroll
        for (int o = 4; o <= 16; o <<= 1) {
            sc0 += __shfl_xor_sync(0xffffffffu, sc0, o);
            sc1 += __shfl_xor_sync(0xffffffffu, sc1, o);
            qc0 += __shfl_xor_sync(0xffffffffu, qc0, o);
            qc1 += __shfl_xor_sync(0xffffffffu, qc1, o);
        }
        if (gr == 0) {
            atomicAdd(&SredS[c0], sc0);
            atomicAdd(&SredS[c0 + 1], sc1);
            atomicAdd(&SredQ[c0], qc0);
            atomicAdd(&SredQ[c0 + 1], qc1);
        }
    }
    __syncthreads();
    if (tid < 128) {
        atomicAdd(&g_stats[layer][tid], SredS[tid]);
        atomicAdd(&g_stats[layer][D + tid], SredQ[tid]);
    }
}

// ---------------- GEMM2: h = relu( relu(BN(x)) @ W2 + b2 ) ----------------
__global__ void __launch_bounds__(256) gemm2_tc_kernel(const float* __restrict__ b2,
                                                       const float* __restrict__ gamma,
                                                       const float* __restrict__ beta,
                                                       int layer) {
    __shared__ SmemGemm sm;
    __shared__ float s_sc[128], s_sh[128];

    int tid = threadIdx.x;
    int lane = tid & 31;
    int wid = tid >> 5;
    int wm = wid & 3;
    int wn = wid >> 2;
    int m0 = blockIdx.x * 64;

    if (tid < 128) {
        float inv = 1.0f / (float)NN;
        float mu = g_stats[layer][tid] * inv;
        float var = g_stats[layer][D + tid] * inv - mu * mu;
        float rs = rsqrtf(var + 1e-5f);
        float sc = rs * __ldg(gamma + (size_t)layer * D + tid);
        s_sc[tid] = sc;
        s_sh[tid] = __ldg(beta + (size_t)layer * D + tid) - mu * sc;
    }
    __syncthreads();

    int lm = tid >> 2;
    int lq = (tid & 3);
    int gm_ld = m0 + lm;
    const unsigned* Wc = &g_w2p[layer][0][0][0][0];

    // prologue chunk 0: A = relu(BN(x)) split
    {
        float4 v = make_float4(0.f, 0.f, 0.f, 0.f);
        if (gm_ld < NN) {
            float4 xv = *(const float4*)(g_x + (size_t)gm_ld * D + lq * 4);
            int c = lq * 4;
            v.x = fmaxf(fmaf(xv.x, s_sc[c + 0], s_sh[c + 0]), 0.f);
            v.y = fmaxf(fmaf(xv.y, s_sc[c + 1], s_sh[c + 1]), 0.f);
            v.z = fmaxf(fmaf(xv.z, s_sc[c + 2], s_sh[c + 2]), 0.f);
            v.w = fmaxf(fmaf(xv.w, s_sc[c + 3], s_sh[c + 3]), 0.f);
        }
        unsigned hi[2], lo[2];
        split4(v, hi, lo);
        sm.A[0][0][lm * 8 + lq * 2] = hi[0];
        sm.A[0][0][lm * 8 + lq * 2 + 1] = hi[1];
        sm.A[0][1][lm * 8 + lq * 2] = lo[0];
        sm.A[0][1][lm * 8 + lq * 2 + 1] = lo[1];
        const uint4* Wg = (const uint4*)Wc;
        uint4 wh = Wg[tid], wl = Wg[tid + 256];
        ((uint4*)sm.B[0][0])[tid] = wh;
        ((uint4*)sm.B[0][1])[tid] = wl;
    }
    __syncthreads();

    float d[8][4];
#pragma unroll
    for (int nt = 0; nt < 8; nt++)
#pragma unroll
        for (int c = 0; c < 4; c++) d[nt][c] = 0.f;

    int kq = lane & 3;
    int gr = lane >> 2;
    int ca = wm * 16 + gr;

#pragma unroll
    for (int kk = 0; kk < 8; kk++) {
        const int cur = kk & 1;
        unsigned nah[2], nal[2];
        uint4 nwh, nwl;
        if (kk < 7) {
            float4 v = make_float4(0.f, 0.f, 0.f, 0.f);
            int kc = (kk + 1) * 16;
            if (gm_ld < NN) {
                float4 xv = *(const float4*)(g_x + (size_t)gm_ld * D + kc + lq * 4);
                int c = kc + lq * 4;
                v.x = fmaxf(fmaf(xv.x, s_sc[c + 0], s_sh[c + 0]), 0.f);
                v.y = fmaxf(fmaf(xv.y, s_sc[c + 1], s_sh[c + 1]), 0.f);
                v.z = fmaxf(fmaf(xv.z, s_sc[c + 2], s_sh[c + 2]), 0.f);
                v.w = fmaxf(fmaf(xv.w, s_sc[c + 3], s_sh[c + 3]), 0.f);
            }
            split4(v, nah, nal);
            const uint4* Wg = (const uint4*)(Wc + (kk + 1) * 2048);
            nwh = Wg[tid]; nwl = Wg[tid + 256];
        }
        unsigned ah[4], al[4];
        ah[0] = sm.A[cur][0][ca * 8 + kq];
        ah[1] = sm.A[cur][0][(ca + 8) * 8 + kq];
        ah[2] = sm.A[cur][0][ca * 8 + kq + 4];
        ah[3] = sm.A[cur][0][(ca + 8) * 8 + kq + 4];
        al[0] = sm.A[cur][1][ca * 8 + kq];
        al[1] = sm.A[cur][1][(ca + 8) * 8 + kq];
        al[2] = sm.A[cur][1][ca * 8 + kq + 4];
        al[3] = sm.A[cur][1][(ca + 8) * 8 + kq + 4];
#pragma unroll
        for (int nt = 0; nt < 8; nt++) {
            int cb = wn * 64 + nt * 8 + gr;
            unsigned bh0 = sm.B[cur][0][cb * 8 + kq];
            unsigned bh1 = sm.B[cur][0][cb * 8 + kq + 4];
            unsigned bl0 = sm.B[cur][1][cb * 8 + kq];
            unsigned bl1 = sm.B[cur][1][cb * 8 + kq + 4];
            mma_bf16(d[nt], ah, bh0, bh1);
            mma_bf16(d[nt], ah, bl0, bl1);
            mma_bf16(d[nt], al, bh0, bh1);
        }
        if (kk < 7) {
            const int nxt = cur ^ 1;
            sm.A[nxt][0][lm * 8 + lq * 2] = nah[0];
            sm.A[nxt][0][lm * 8 + lq * 2 + 1] = nah[1];
            sm.A[nxt][1][lm * 8 + lq * 2] = nal[0];
            sm.A[nxt][1][lm * 8 + lq * 2 + 1] = nal[1];
            ((uint4*)sm.B[nxt][0])[tid] = nwh;
            ((uint4*)sm.B[nxt][1])[tid] = nwl;
            __syncthreads();
        }
    }

    // epilogue: relu(d + b2) -> g_h
    int r0 = m0 + wm * 16 + gr;
    int r1 = r0 + 8;
#pragma unroll
    for (int nt = 0; nt < 8; nt++) {
        int c0 = wn * 64 + nt * 8 + 2 * kq;
        float bb0 = __ldg(b2 + (size_t)layer * D + c0);
        float bb1 = __ldg(b2 + (size_t)layer * D + c0 + 1);
        if (r0 < NN) {
            float2 v = make_float2(fmaxf(d[nt][0] + bb0, 0.f),
                                   fmaxf(d[nt][1] + bb1, 0.f));
            *(float2*)(g_h + (size_t)r0 * D + c0) = v;
        }
        if (r1 < NN) {
            float2 v = make_float2(fmaxf(d[nt][2] + bb0, 0.f),
                                   fmaxf(d[nt][3] + bb1, 0.f));
            *(float2*)(g_h + (size_t)r1 * D + c0) = v;
        }
    }
}

// ---------------- GEMM3 (final, FFMA fp32): out = h @ Wout + bout ----------------
__global__ void __launch_bounds__(256) gemm3_kernel(const float* __restrict__ Wout,
                                                    const float* __restrict__ bout,
                                                    float* __restrict__ out) {
    __shared__ float Bs[16][64];
    __shared__ float As[16][68];

    int tid = threadIdx.x;
    int tn = tid & 15;
    int tm = tid >> 4;
    int m0 = blockIdx.x * 64;

    float acc[4][4];
#pragma unroll
    for (int r = 0; r < 4; r++)
#pragma unroll
        for (int c = 0; c < 4; c++) acc[r][c] = 0.f;

    int lm = tid >> 2;
    int lk = (tid & 3) * 4;
    int gm_ld = m0 + lm;

    for (int kk = 0; kk < D; kk += 16) {
        {
            const float4* Wv = (const float4*)(Wout + kk * OD);
            float4* Bv = (float4*)&Bs[0][0];
            Bv[tid] = Wv[tid];
        }
        {
            float4 a = make_float4(0.f, 0.f, 0.f, 0.f);
            if (gm_ld < NN) {
                a = *(const float4*)(g_h + (size_t)gm_ld * D + kk + lk);
            }
            As[lk + 0][lm] = a.x;
            As[lk + 1][lm] = a.y;
            As[lk + 2][lm] = a.z;
            As[lk + 3][lm] = a.w;
        }
        __syncthreads();
#pragma unroll
        for (int k = 0; k < 16; k++) {
            float4 b = *(const float4*)(&Bs[k][tn * 4]);
            float4 a = *(const float4*)(&As[k][tm * 4]);
            float av[4] = {a.x, a.y, a.z, a.w};
#pragma unroll
            for (int r = 0; r < 4; r++) {
                acc[r][0] = fmaf(av[r], b.x, acc[r][0]);
                acc[r][1] = fmaf(av[r], b.y, acc[r][1]);
                acc[r][2] = fmaf(av[r], b.z, acc[r][2]);
                acc[r][3] = fmaf(av[r], b.w, acc[r][3]);
            }
        }
        __syncthreads();
    }

    float4 bb = *(const float4*)(bout + tn * 4);
#pragma unroll
    for (int r = 0; r < 4; r++) {
        int gm = m0 + tm * 4 + r;
        if (gm < NN) {
            float4 v;
            v.x = acc[r][0] + bb.x;
            v.y = acc[r][1] + bb.y;
            v.z = acc[r][2] + bb.z;
            v.w = acc[r][3] + bb.w;
            *(float4*)(out + (size_t)gm * OD + tn * 4) = v;
        }
    }
}

// ---------------- launch ----------------
extern "C" void kernel_launch(void* const* d_in, const int* in_sizes, int n_in,
                              void* d_out, int out_size) {
    const float* node_feat = (const float*)d_in[0];
    const int*   src       = (const int*)d_in[1];
    const int*   dst       = (const int*)d_in[2];
    const float* W1        = (const float*)d_in[3];
    const float* b1        = (const float*)d_in[4];
    const float* gamma     = (const float*)d_in[5];
    const float* beta      = (const float*)d_in[6];
    const float* W2        = (const float*)d_in[7];
    const float* b2        = (const float*)d_in[8];
    const float* eps       = (const float*)d_in[9];
    const float* Wout      = (const float*)d_in[10];
    const float* bout      = (const float*)d_in[11];
    float* out = (float*)d_out;

    const int gemm_grid  = (NN + 63) / 64;          // 782
    const int edge4_grid = (NE / 4 + 255) / 256;    // 1563
    const int node_grid  = (NN + 255) / 256;        // 196
    const int gath_grid  = (NN + 7) / 8;            // 6250
    const int cvtw_grid  = (NL * 64 * 128 + 255) / 256;

    csr_zero_kernel<<<node_grid, 256>>>();
    cvt_w_kernel<<<cvtw_grid, 256>>>(W1, W2);
    csr_hist_kernel<<<edge4_grid, 256>>>(dst);
    scan1_kernel<<<NBLK, 256>>>();
    scan2_kernel<<<1, 256>>>();
    scan3_kernel<<<NBLK, 256>>>();
    csr_fill_kernel<<<edge4_grid, 256>>>(src, dst);

    for (int l = 0; l < NL; l++) {
        gather_kernel<<<gath_grid, 256>>>(node_feat, eps, l);
        gemm1_tc_kernel<<<gemm_grid, 256>>>(b1, l);
        gemm2_tc_kernel<<<gemm_grid, 256>>>(b2, gamma, beta, l);
    }
    gemm3_kernel<<<gemm_grid, 256>>>(Wout, bout, out);
}

// round 9
// speedup vs baseline: 2.6751x; 1.0930x over previous
#include <cuda_runtime.h>
#include <cuda_bf16.h>
#include <cuda_fp16.h>

#define NN 50000
#define NE 1600000
#define D  128
#define OD 64
#define NL 3
#define NBLK 196   // ceil(NN/256)

// ---------------- device scratch ----------------
__device__ __half g_hh[NN * D];        // node features (fp16) — gather/gemm3 input
__device__ float g_x[NN * D];          // MLP hidden pre-BN (fp32)
__device__ float g_xin[NN * D];        // (1+eps)h + agg (fp32)
__device__ float g_stats[NL][2 * D];   // per-layer per-channel sum & sumsq

// Pre-split weights, smem image layout:
// [layer][chunk(8)][hi/lo(2)][n(128)][kpair(8)]  (each uint = 2 bf16, low = even k)
__device__ unsigned g_w1p[NL][8][2][128][8];
__device__ unsigned g_w2p[NL][8][2][128][8];

// CSR
__device__ int g_cnt[NN];
__device__ int g_cur[NN];
__device__ int g_off[NN + 1];
__device__ int g_csrc[NE];
__device__ int g_bsum[NBLK + 1];

__device__ __forceinline__ unsigned pack_bf2(float a, float b) {
    __nv_bfloat162 t = __floats2bfloat162_rn(a, b);
    return *reinterpret_cast<unsigned*>(&t);
}
__device__ __forceinline__ float bf_hi(float x) {
    return __bfloat162float(__float2bfloat16_rn(x));
}
__device__ __forceinline__ float4 h4_to_f4(uint2 u) {
    __half2 a = *reinterpret_cast<__half2*>(&u.x);
    __half2 b = *reinterpret_cast<__half2*>(&u.y);
    float2 fa = __half22float2(a), fb = __half22float2(b);
    return make_float4(fa.x, fa.y, fb.x, fb.y);
}

__device__ __forceinline__ void mma_bf16(float* d, const unsigned* a,
                                         unsigned b0, unsigned b1) {
    asm volatile(
        "mma.sync.aligned.m16n8k16.row.col.f32.bf16.bf16.f32 "
        "{%0,%1,%2,%3}, {%4,%5,%6,%7}, {%8,%9}, {%0,%1,%2,%3};"
        : "+f"(d[0]), "+f"(d[1]), "+f"(d[2]), "+f"(d[3])
        : "r"(a[0]), "r"(a[1]), "r"(a[2]), "r"(a[3]), "r"(b0), "r"(b1));
}

// ---------------- init kernels ----------------
__global__ void csr_zero_kernel() {
    int i = blockIdx.x * blockDim.x + threadIdx.x;
    if (i < NN) g_cnt[i] = 0;
    if (i == 0) g_off[0] = 0;
    if (i < NL * 2 * D) ((float*)g_stats)[i] = 0.f;
}

// node_feat (fp32) -> g_hh (fp16), 4 elements per thread
__global__ void cvt_nf_kernel(const float* __restrict__ nf) {
    int i = blockIdx.x * blockDim.x + threadIdx.x;
    if (i >= NN * D / 4) return;
    float4 v = __ldg((const float4*)nf + i);
    __half2* p = (__half2*)g_hh + i * 2;
    p[0] = __floats2half2_rn(v.x, v.y);
    p[1] = __floats2half2_rn(v.z, v.w);
}

// Pre-split weights into hi/lo bf16 pairs (smem-image layout)
__global__ void cvt_w_kernel(const float* __restrict__ W1,
                             const float* __restrict__ W2) {
    int i = blockIdx.x * blockDim.x + threadIdx.x;
    if (i >= NL * 64 * 128) return;
    int n = i & 127;
    int kp = (i >> 7) & 63;
    int l = i >> 13;
    int k0 = kp * 2;
    int chunk = k0 >> 4;
    int kpi = (k0 & 15) >> 1;

    {
        float w0 = __ldg(W1 + (size_t)l * D * D + k0 * D + n);
        float w1 = __ldg(W1 + (size_t)l * D * D + (k0 + 1) * D + n);
        float h0 = bf_hi(w0), h1 = bf_hi(w1);
        g_w1p[l][chunk][0][n][kpi] = pack_bf2(h0, h1);
        g_w1p[l][chunk][1][n][kpi] = pack_bf2(w0 - h0, w1 - h1);
    }
    {
        float w0 = __ldg(W2 + (size_t)l * D * D + k0 * D + n);
        float w1 = __ldg(W2 + (size_t)l * D * D + (k0 + 1) * D + n);
        float h0 = bf_hi(w0), h1 = bf_hi(w1);
        g_w2p[l][chunk][0][n][kpi] = pack_bf2(h0, h1);
        g_w2p[l][chunk][1][n][kpi] = pack_bf2(w0 - h0, w1 - h1);
    }
}

__global__ void csr_hist_kernel(const int* __restrict__ dst) {
    int i = blockIdx.x * blockDim.x + threadIdx.x;
    if (i >= NE / 4) return;
    int4 d = __ldg((const int4*)dst + i);
    atomicAdd(&g_cnt[d.x], 1);
    atomicAdd(&g_cnt[d.y], 1);
    atomicAdd(&g_cnt[d.z], 1);
    atomicAdd(&g_cnt[d.w], 1);
}

// --- hierarchical scan ---
__global__ void scan1_kernel() {
    int b = blockIdx.x, tid = threadIdx.x;
    int i = b * 256 + tid;
    int v = (i < NN) ? g_cnt[i] : 0;
    int lane = tid & 31, w = tid >> 5;
    int x = v;
#pragma unroll
    for (int o = 1; o < 32; o <<= 1) {
        int t = __shfl_up_sync(0xffffffffu, x, o);
        if (lane >= o) x += t;
    }
    __shared__ int wsum[8];
    if (lane == 31) wsum[w] = x;
    __syncthreads();
    if (w == 0 && lane < 8) {
        int y = wsum[lane];
#pragma unroll
        for (int o = 1; o < 8; o <<= 1) {
            int t = __shfl_up_sync(0xffu, y, o);
            if (lane >= o) y += t;
        }
        wsum[lane] = y;
    }
    __syncthreads();
    int incl = x + (w > 0 ? wsum[w - 1] : 0);
    if (i < NN) {
        g_off[i + 1] = incl;
        g_cur[i] = incl - v;
    }
    if (tid == 255) g_bsum[b] = incl;
}

__global__ void scan2_kernel() {
    int tid = threadIdx.x;
    int lane = tid & 31, w = tid >> 5;
    int v = (tid < NBLK) ? g_bsum[tid] : 0;
    int x = v;
#pragma unroll
    for (int o = 1; o < 32; o <<= 1) {
        int t = __shfl_up_sync(0xffffffffu, x, o);
        if (lane >= o) x += t;
    }
    __shared__ int wsum[8];
    if (lane == 31) wsum[w] = x;
    __syncthreads();
    if (w == 0 && lane < 8) {
        int y = wsum[lane];
#pragma unroll
        for (int o = 1; o < 8; o <<= 1) {
            int t = __shfl_up_sync(0xffu, y, o);
            if (lane >= o) y += t;
        }
        wsum[lane] = y;
    }
    __syncthreads();
    int incl = x + (w > 0 ? wsum[w - 1] : 0);
    if (tid < NBLK) g_bsum[tid] = incl - v;
}

__global__ void scan3_kernel() {
    int b = blockIdx.x;
    int i = b * 256 + threadIdx.x;
    if (i < NN) {
        int base = g_bsum[b];
        g_off[i + 1] += base;
        g_cur[i] += base;
    }
}

__global__ void csr_fill_kernel(const int* __restrict__ src,
                                const int* __restrict__ dst) {
    int i = blockIdx.x * blockDim.x + threadIdx.x;
    if (i >= NE / 4) return;
    int4 s = __ldg((const int4*)src + i);
    int4 d = __ldg((const int4*)dst + i);
    int p0 = atomicAdd(&g_cur[d.x], 1);
    int p1 = atomicAdd(&g_cur[d.y], 1);
    int p2 = atomicAdd(&g_cur[d.z], 1);
    int p3 = atomicAdd(&g_cur[d.w], 1);
    g_csrc[p0] = s.x;
    g_csrc[p1] = s.y;
    g_csrc[p2] = s.z;
    g_csrc[p3] = s.w;
}

// ---------------- gather (fp16 h): xin = (1+eps)h + sum_nbr h, fp32 accum ----------------
// warp-per-node; each lane owns 4 channels (8 bytes/row) -> 256B coalesced per neighbor.
__global__ void __launch_bounds__(256) gather_kernel(const float* __restrict__ eps,
                                                     int layer) {
    int node = blockIdx.x * 8 + (threadIdx.x >> 5);
    if (node >= NN) return;
    int lane = threadIdx.x & 31;
    float oe = 1.0f + __ldg(eps + layer);

    int beg = g_off[node];
    int end = g_off[node + 1];

    const __half* hb = g_hh;
    float4 hv = h4_to_f4(*(const uint2*)(hb + (size_t)node * D + lane * 4));
    float4 acc;
    acc.x = oe * hv.x; acc.y = oe * hv.y; acc.z = oe * hv.z; acc.w = oe * hv.w;

    int i = beg;
    for (; i + 3 < end; i += 4) {
        int s0 = __ldg(g_csrc + i);
        int s1 = __ldg(g_csrc + i + 1);
        int s2 = __ldg(g_csrc + i + 2);
        int s3 = __ldg(g_csrc + i + 3);
        float4 v0 = h4_to_f4(*(const uint2*)(hb + (size_t)s0 * D + lane * 4));
        float4 v1 = h4_to_f4(*(const uint2*)(hb + (size_t)s1 * D + lane * 4));
        float4 v2 = h4_to_f4(*(const uint2*)(hb + (size_t)s2 * D + lane * 4));
        float4 v3 = h4_to_f4(*(const uint2*)(hb + (size_t)s3 * D + lane * 4));
        acc.x += v0.x + v1.x + v2.x + v3.x;
        acc.y += v0.y + v1.y + v2.y + v3.y;
        acc.z += v0.z + v1.z + v2.z + v3.z;
        acc.w += v0.w + v1.w + v2.w + v3.w;
    }
    for (; i < end; i++) {
        int s = __ldg(g_csrc + i);
        float4 v = h4_to_f4(*(const uint2*)(hb + (size_t)s * D + lane * 4));
        acc.x += v.x; acc.y += v.y; acc.z += v.z; acc.w += v.w;
    }
    *(float4*)(g_xin + (size_t)node * D + lane * 4) = acc;
}

// =====================================================================
// Split-bf16 tensor-core GEMM core.
// =====================================================================

struct SmemGemm {
    unsigned A[2][2][64 * 8];    // [buf][hi/lo][m*8 + kpair]
    unsigned B[2][2][128 * 8];   // [buf][hi/lo][n*8 + kpair]
};

__device__ __forceinline__ void split4(float4 v, unsigned* hi, unsigned* lo) {
    float h0 = bf_hi(v.x), h1 = bf_hi(v.y), h2 = bf_hi(v.z), h3 = bf_hi(v.w);
    hi[0] = pack_bf2(h0, h1);
    hi[1] = pack_bf2(h2, h3);
    lo[0] = pack_bf2(v.x - h0, v.y - h1);
    lo[1] = pack_bf2(v.z - h2, v.w - h3);
}

// ---------------- GEMM1: x = xin @ W1 + b1, + BN stats ----------------
__global__ void __launch_bounds__(256) gemm1_tc_kernel(const float* __restrict__ b1,
                                                       int layer) {
    __shared__ SmemGemm sm;
    __shared__ float SredS[128], SredQ[128];

    int tid = threadIdx.x;
    int lane = tid & 31;
    int wid = tid >> 5;
    int wm = wid & 3;
    int wn = wid >> 2;
    int m0 = blockIdx.x * 64;

    if (tid < 128) { SredS[tid] = 0.f; SredQ[tid] = 0.f; }

    int lm = tid >> 2;
    int lq = (tid & 3);
    int gm_ld = m0 + lm;
    const unsigned* Wc = &g_w1p[layer][0][0][0][0];

    // prologue: chunk 0
    {
        float4 v = make_float4(0.f, 0.f, 0.f, 0.f);
        if (gm_ld < NN) v = *(const float4*)(g_xin + (size_t)gm_ld * D + lq * 4);
        unsigned hi[2], lo[2];
        split4(v, hi, lo);
        sm.A[0][0][lm * 8 + lq * 2] = hi[0];
        sm.A[0][0][lm * 8 + lq * 2 + 1] = hi[1];
        sm.A[0][1][lm * 8 + lq * 2] = lo[0];
        sm.A[0][1][lm * 8 + lq * 2 + 1] = lo[1];
        const uint4* Wg = (const uint4*)Wc;
        uint4 wh = Wg[tid], wl = Wg[tid + 256];
        ((uint4*)sm.B[0][0])[tid] = wh;
        ((uint4*)sm.B[0][1])[tid] = wl;
    }
    __syncthreads();

    float d[8][4];
#pragma unroll
    for (int nt = 0; nt < 8; nt++)
#pragma unroll
        for (int c = 0; c < 4; c++) d[nt][c] = 0.f;

    int kq = lane & 3;
    int gr = lane >> 2;
    int ca = wm * 16 + gr;

#pragma unroll
    for (int kk = 0; kk < 8; kk++) {
        const int cur = kk & 1;
        unsigned nah[2], nal[2];
        uint4 nwh, nwl;
        if (kk < 7) {
            float4 v = make_float4(0.f, 0.f, 0.f, 0.f);
            if (gm_ld < NN)
                v = *(const float4*)(g_xin + (size_t)gm_ld * D + (kk + 1) * 16 + lq * 4);
            split4(v, nah, nal);
            const uint4* Wg = (const uint4*)(Wc + (kk + 1) * 2048);
            nwh = Wg[tid]; nwl = Wg[tid + 256];
        }
        unsigned ah[4], al[4];
        ah[0] = sm.A[cur][0][ca * 8 + kq];
        ah[1] = sm.A[cur][0][(ca + 8) * 8 + kq];
        ah[2] = sm.A[cur][0][ca * 8 + kq + 4];
        ah[3] = sm.A[cur][0][(ca + 8) * 8 + kq + 4];
        al[0] = sm.A[cur][1][ca * 8 + kq];
        al[1] = sm.A[cur][1][(ca + 8) * 8 + kq];
        al[2] = sm.A[cur][1][ca * 8 + kq + 4];
        al[3] = sm.A[cur][1][(ca + 8) * 8 + kq + 4];
#pragma unroll
        for (int nt = 0; nt < 8; nt++) {
            int cb = wn * 64 + nt * 8 + gr;
            unsigned bh0 = sm.B[cur][0][cb * 8 + kq];
            unsigned bh1 = sm.B[cur][0][cb * 8 + kq + 4];
            unsigned bl0 = sm.B[cur][1][cb * 8 + kq];
            unsigned bl1 = sm.B[cur][1][cb * 8 + kq + 4];
            mma_bf16(d[nt], ah, bh0, bh1);
            mma_bf16(d[nt], ah, bl0, bl1);
            mma_bf16(d[nt], al, bh0, bh1);
        }
        if (kk < 7) {
            const int nxt = cur ^ 1;
            sm.A[nxt][0][lm * 8 + lq * 2] = nah[0];
            sm.A[nxt][0][lm * 8 + lq * 2 + 1] = nah[1];
            sm.A[nxt][1][lm * 8 + lq * 2] = nal[0];
            sm.A[nxt][1][lm * 8 + lq * 2 + 1] = nal[1];
            ((uint4*)sm.B[nxt][0])[tid] = nwh;
            ((uint4*)sm.B[nxt][1])[tid] = nwl;
            __syncthreads();
        }
    }

    // epilogue: bias, store x, BN stats
    int r0 = m0 + wm * 16 + gr;
    int r1 = r0 + 8;
    bool v0r = (r0 < NN), v1r = (r1 < NN);
#pragma unroll
    for (int nt = 0; nt < 8; nt++) {
        int c0 = wn * 64 + nt * 8 + 2 * kq;
        float bb0 = __ldg(b1 + (size_t)layer * D + c0);
        float bb1 = __ldg(b1 + (size_t)layer * D + c0 + 1);
        float x0 = d[nt][0] + bb0, x1 = d[nt][1] + bb1;
        float x2 = d[nt][2] + bb0, x3 = d[nt][3] + bb1;
        if (v0r) *(float2*)(g_x + (size_t)r0 * D + c0) = make_float2(x0, x1);
        if (v1r) *(float2*)(g_x + (size_t)r1 * D + c0) = make_float2(x2, x3);
        float sc0 = (v0r ? x0 : 0.f) + (v1r ? x2 : 0.f);
        float sc1 = (v0r ? x1 : 0.f) + (v1r ? x3 : 0.f);
        float qc0 = (v0r ? x0 * x0 : 0.f) + (v1r ? x2 * x2 : 0.f);
        float qc1 = (v0r ? x1 * x1 : 0.f) + (v1r ? x3 * x3 : 0.f);
#pragma unroll
        for (int o = 4; o <= 16; o <<= 1) {
            sc0 += __shfl_xor_sync(0xffffffffu, sc0, o);
            sc1 += __shfl_xor_sync(0xffffffffu, sc1, o);
            qc0 += __shfl_xor_sync(0xffffffffu, qc0, o);
            qc1 += __shfl_xor_sync(0xffffffffu, qc1, o);
        }
        if (gr == 0) {
            atomicAdd(&SredS[c0], sc0);
            atomicAdd(&SredS[c0 + 1], sc1);
            atomicAdd(&SredQ[c0], qc0);
            atomicAdd(&SredQ[c0 + 1], qc1);
        }
    }
    __syncthreads();
    if (tid < 128) {
        atomicAdd(&g_stats[layer][tid], SredS[tid]);
        atomicAdd(&g_stats[layer][D + tid], SredQ[tid]);
    }
}

// ---------------- GEMM2: h = relu( relu(BN(x)) @ W2 + b2 ) -> fp16 g_hh ----------------
__global__ void __launch_bounds__(256) gemm2_tc_kernel(const float* __restrict__ b2,
                                                       const float* __restrict__ gamma,
                                                       const float* __restrict__ beta,
                                                       int layer) {
    __shared__ SmemGemm sm;
    __shared__ float s_sc[128], s_sh[128];

    int tid = threadIdx.x;
    int lane = tid & 31;
    int wid = tid >> 5;
    int wm = wid & 3;
    int wn = wid >> 2;
    int m0 = blockIdx.x * 64;

    if (tid < 128) {
        float inv = 1.0f / (float)NN;
        float mu = g_stats[layer][tid] * inv;
        float var = g_stats[layer][D + tid] * inv - mu * mu;
        float rs = rsqrtf(var + 1e-5f);
        float sc = rs * __ldg(gamma + (size_t)layer * D + tid);
        s_sc[tid] = sc;
        s_sh[tid] = __ldg(beta + (size_t)layer * D + tid) - mu * sc;
    }
    __syncthreads();

    int lm = tid >> 2;
    int lq = (tid & 3);
    int gm_ld = m0 + lm;
    const unsigned* Wc = &g_w2p[layer][0][0][0][0];

    // prologue chunk 0: A = relu(BN(x)) split
    {
        float4 v = make_float4(0.f, 0.f, 0.f, 0.f);
        if (gm_ld < NN) {
            float4 xv = *(const float4*)(g_x + (size_t)gm_ld * D + lq * 4);
            int c = lq * 4;
            v.x = fmaxf(fmaf(xv.x, s_sc[c + 0], s_sh[c + 0]), 0.f);
            v.y = fmaxf(fmaf(xv.y, s_sc[c + 1], s_sh[c + 1]), 0.f);
            v.z = fmaxf(fmaf(xv.z, s_sc[c + 2], s_sh[c + 2]), 0.f);
            v.w = fmaxf(fmaf(xv.w, s_sc[c + 3], s_sh[c + 3]), 0.f);
        }
        unsigned hi[2], lo[2];
        split4(v, hi, lo);
        sm.A[0][0][lm * 8 + lq * 2] = hi[0];
        sm.A[0][0][lm * 8 + lq * 2 + 1] = hi[1];
        sm.A[0][1][lm * 8 + lq * 2] = lo[0];
        sm.A[0][1][lm * 8 + lq * 2 + 1] = lo[1];
        const uint4* Wg = (const uint4*)Wc;
        uint4 wh = Wg[tid], wl = Wg[tid + 256];
        ((uint4*)sm.B[0][0])[tid] = wh;
        ((uint4*)sm.B[0][1])[tid] = wl;
    }
    __syncthreads();

    float d[8][4];
#pragma unroll
    for (int nt = 0; nt < 8; nt++)
#pragma unroll
        for (int c = 0; c < 4; c++) d[nt][c] = 0.f;

    int kq = lane & 3;
    int gr = lane >> 2;
    int ca = wm * 16 + gr;

#pragma unroll
    for (int kk = 0; kk < 8; kk++) {
        const int cur = kk & 1;
        unsigned nah[2], nal[2];
        uint4 nwh, nwl;
        if (kk < 7) {
            float4 v = make_float4(0.f, 0.f, 0.f, 0.f);
            int kc = (kk + 1) * 16;
            if (gm_ld < NN) {
                float4 xv = *(const float4*)(g_x + (size_t)gm_ld * D + kc + lq * 4);
                int c = kc + lq * 4;
                v.x = fmaxf(fmaf(xv.x, s_sc[c + 0], s_sh[c + 0]), 0.f);
                v.y = fmaxf(fmaf(xv.y, s_sc[c + 1], s_sh[c + 1]), 0.f);
                v.z = fmaxf(fmaf(xv.z, s_sc[c + 2], s_sh[c + 2]), 0.f);
                v.w = fmaxf(fmaf(xv.w, s_sc[c + 3], s_sh[c + 3]), 0.f);
            }
            split4(v, nah, nal);
            const uint4* Wg = (const uint4*)(Wc + (kk + 1) * 2048);
            nwh = Wg[tid]; nwl = Wg[tid + 256];
        }
        unsigned ah[4], al[4];
        ah[0] = sm.A[cur][0][ca * 8 + kq];
        ah[1] = sm.A[cur][0][(ca + 8) * 8 + kq];
        ah[2] = sm.A[cur][0][ca * 8 + kq + 4];
        ah[3] = sm.A[cur][0][(ca + 8) * 8 + kq + 4];
        al[0] = sm.A[cur][1][ca * 8 + kq];
        al[1] = sm.A[cur][1][(ca + 8) * 8 + kq];
        al[2] = sm.A[cur][1][ca * 8 + kq + 4];
        al[3] = sm.A[cur][1][(ca + 8) * 8 + kq + 4];
#pragma unroll
        for (int nt = 0; nt < 8; nt++) {
            int cb = wn * 64 + nt * 8 + gr;
            unsigned bh0 = sm.B[cur][0][cb * 8 + kq];
            unsigned bh1 = sm.B[cur][0][cb * 8 + kq + 4];
            unsigned bl0 = sm.B[cur][1][cb * 8 + kq];
            unsigned bl1 = sm.B[cur][1][cb * 8 + kq + 4];
            mma_bf16(d[nt], ah, bh0, bh1);
            mma_bf16(d[nt], ah, bl0, bl1);
            mma_bf16(d[nt], al, bh0, bh1);
        }
        if (kk < 7) {
            const int nxt = cur ^ 1;
            sm.A[nxt][0][lm * 8 + lq * 2] = nah[0];
            sm.A[nxt][0][lm * 8 + lq * 2 + 1] = nah[1];
            sm.A[nxt][1][lm * 8 + lq * 2] = nal[0];
            sm.A[nxt][1][lm * 8 + lq * 2 + 1] = nal[1];
            ((uint4*)sm.B[nxt][0])[tid] = nwh;
            ((uint4*)sm.B[nxt][1])[tid] = nwl;
            __syncthreads();
        }
    }

    // epilogue: relu(d + b2) -> g_hh (fp16)
    int r0 = m0 + wm * 16 + gr;
    int r1 = r0 + 8;
#pragma unroll
    for (int nt = 0; nt < 8; nt++) {
        int c0 = wn * 64 + nt * 8 + 2 * kq;
        float bb0 = __ldg(b2 + (size_t)layer * D + c0);
        float bb1 = __ldg(b2 + (size_t)layer * D + c0 + 1);
        if (r0 < NN) {
            *(__half2*)(g_hh + (size_t)r0 * D + c0) =
                __floats2half2_rn(fmaxf(d[nt][0] + bb0, 0.f),
                                  fmaxf(d[nt][1] + bb1, 0.f));
        }
        if (r1 < NN) {
            *(__half2*)(g_hh + (size_t)r1 * D + c0) =
                __floats2half2_rn(fmaxf(d[nt][2] + bb0, 0.f),
                                  fmaxf(d[nt][3] + bb1, 0.f));
        }
    }
}

// ---------------- GEMM3 (final, FFMA fp32, fp16 A): out = h @ Wout + bout ----------------
__global__ void __launch_bounds__(256) gemm3_kernel(const float* __restrict__ Wout,
                                                    const float* __restrict__ bout,
                                                    float* __restrict__ out) {
    __shared__ float Bs[16][64];
    __shared__ float As[16][68];

    int tid = threadIdx.x;
    int tn = tid & 15;
    int tm = tid >> 4;
    int m0 = blockIdx.x * 64;

    float acc[4][4];
#pragma unroll
    for (int r = 0; r < 4; r++)
#pragma unroll
        for (int c = 0; c < 4; c++) acc[r][c] = 0.f;

    int lm = tid >> 2;
    int lk = (tid & 3) * 4;
    int gm_ld = m0 + lm;

    for (int kk = 0; kk < D; kk += 16) {
        {
            const float4* Wv = (const float4*)(Wout + kk * OD);
            float4* Bv = (float4*)&Bs[0][0];
            Bv[tid] = Wv[tid];
        }
        {
            float4 a = make_float4(0.f, 0.f, 0.f, 0.f);
            if (gm_ld < NN) {
                a = h4_to_f4(*(const uint2*)(g_hh + (size_t)gm_ld * D + kk + lk));
            }
            As[lk + 0][lm] = a.x;
            As[lk + 1][lm] = a.y;
            As[lk + 2][lm] = a.z;
            As[lk + 3][lm] = a.w;
        }
        __syncthreads();
#pragma unroll
        for (int k = 0; k < 16; k++) {
            float4 b = *(const float4*)(&Bs[k][tn * 4]);
            float4 a = *(const float4*)(&As[k][tm * 4]);
            float av[4] = {a.x, a.y, a.z, a.w};
#pragma unroll
            for (int r = 0; r < 4; r++) {
                acc[r][0] = fmaf(av[r], b.x, acc[r][0]);
                acc[r][1] = fmaf(av[r], b.y, acc[r][1]);
                acc[r][2] = fmaf(av[r], b.z, acc[r][2]);
                acc[r][3] = fmaf(av[r], b.w, acc[r][3]);
            }
        }
        __syncthreads();
    }

    float4 bb = *(const float4*)(bout + tn * 4);
#pragma unroll
    for (int r = 0; r < 4; r++) {
        int gm = m0 + tm * 4 + r;
        if (gm < NN) {
            float4 v;
            v.x = acc[r][0] + bb.x;
            v.y = acc[r][1] + bb.y;
            v.z = acc[r][2] + bb.z;
            v.w = acc[r][3] + bb.w;
            *(float4*)(out + (size_t)gm * OD + tn * 4) = v;
        }
    }
}

// ---------------- launch ----------------
extern "C" void kernel_launch(void* const* d_in, const int* in_sizes, int n_in,
                              void* d_out, int out_size) {
    const float* node_feat = (const float*)d_in[0];
    const int*   src       = (const int*)d_in[1];
    const int*   dst       = (const int*)d_in[2];
    const float* W1        = (const float*)d_in[3];
    const float* b1        = (const float*)d_in[4];
    const float* gamma     = (const float*)d_in[5];
    const float* beta      = (const float*)d_in[6];
    const float* W2        = (const float*)d_in[7];
    const float* b2        = (const float*)d_in[8];
    const float* eps       = (const float*)d_in[9];
    const float* Wout      = (const float*)d_in[10];
    const float* bout      = (const float*)d_in[11];
    float* out = (float*)d_out;

    const int gemm_grid  = (NN + 63) / 64;          // 782
    const int edge4_grid = (NE / 4 + 255) / 256;    // 1563
    const int node_grid  = (NN + 255) / 256;        // 196
    const int gath_grid  = (NN + 7) / 8;            // 6250
    const int cvtw_grid  = (NL * 64 * 128 + 255) / 256;
    const int cvtn_grid  = (NN * D / 4 + 255) / 256;

    csr_zero_kernel<<<node_grid, 256>>>();
    cvt_nf_kernel<<<cvtn_grid, 256>>>(node_feat);
    cvt_w_kernel<<<cvtw_grid, 256>>>(W1, W2);
    csr_hist_kernel<<<edge4_grid, 256>>>(dst);
    scan1_kernel<<<NBLK, 256>>>();
    scan2_kernel<<<1, 256>>>();
    scan3_kernel<<<NBLK, 256>>>();
    csr_fill_kernel<<<edge4_grid, 256>>>(src, dst);

    for (int l = 0; l < NL; l++) {
        gather_kernel<<<gath_grid, 256>>>(eps, l);
        gemm1_tc_kernel<<<gemm_grid, 256>>>(b1, l);
        gemm2_tc_kernel<<<gemm_grid, 256>>>(b2, gamma, beta, l);
    }
    gemm3_kernel<<<gemm_grid, 256>>>(Wout, bout, out);
}

// round 10
// speedup vs baseline: 2.7733x; 1.0367x over previous
#include <cuda_runtime.h>
#include <cuda_bf16.h>
#include <cuda_fp16.h>

#define NN 50000
#define NE 1600000
#define D  128
#define OD 64
#define NL 3
#define NBLK 196   // ceil(NN/256)

// ---------------- device scratch ----------------
__device__ __half g_hh[NN * D];        // node features (fp16) — gather/gemm3 input
__device__ float g_x[NN * D];          // MLP hidden pre-BN (fp32)
__device__ float g_xin[NN * D];        // (1+eps)h + agg (fp32)
__device__ float g_stats[NL][2 * D];   // per-layer per-channel sum & sumsq

// Pre-split weights, smem image layout:
// [layer][chunk(8)][hi/lo(2)][n(128)][kpair(8)]  (each uint = 2 bf16, low = even k)
__device__ unsigned g_w1p[NL][8][2][128][8];
__device__ unsigned g_w2p[NL][8][2][128][8];
// Wout in fp16, smem image: [chunk(8)][n(64)][kpair(8)] (uint = 2 fp16)
__device__ unsigned g_w3p[8][64][8];

// CSR
__device__ int g_cnt[NN];
__device__ int g_cur[NN];
__device__ int g_off[NN + 1];
__device__ int g_csrc[NE];
__device__ int g_bsum[NBLK + 1];

__device__ __forceinline__ unsigned pack_bf2(float a, float b) {
    __nv_bfloat162 t = __floats2bfloat162_rn(a, b);
    return *reinterpret_cast<unsigned*>(&t);
}
__device__ __forceinline__ unsigned pack_h2(float a, float b) {
    __half2 t = __floats2half2_rn(a, b);
    return *reinterpret_cast<unsigned*>(&t);
}
__device__ __forceinline__ float bf_hi(float x) {
    return __bfloat162float(__float2bfloat16_rn(x));
}
__device__ __forceinline__ float4 h4_to_f4(uint2 u) {
    __half2 a = *reinterpret_cast<__half2*>(&u.x);
    __half2 b = *reinterpret_cast<__half2*>(&u.y);
    float2 fa = __half22float2(a), fb = __half22float2(b);
    return make_float4(fa.x, fa.y, fb.x, fb.y);
}

__device__ __forceinline__ void mma_bf16(float* d, const unsigned* a,
                                         unsigned b0, unsigned b1) {
    asm volatile(
        "mma.sync.aligned.m16n8k16.row.col.f32.bf16.bf16.f32 "
        "{%0,%1,%2,%3}, {%4,%5,%6,%7}, {%8,%9}, {%0,%1,%2,%3};"
        : "+f"(d[0]), "+f"(d[1]), "+f"(d[2]), "+f"(d[3])
        : "r"(a[0]), "r"(a[1]), "r"(a[2]), "r"(a[3]), "r"(b0), "r"(b1));
}
__device__ __forceinline__ void mma_f16(float* d, const unsigned* a,
                                        unsigned b0, unsigned b1) {
    asm volatile(
        "mma.sync.aligned.m16n8k16.row.col.f32.f16.f16.f32 "
        "{%0,%1,%2,%3}, {%4,%5,%6,%7}, {%8,%9}, {%0,%1,%2,%3};"
        : "+f"(d[0]), "+f"(d[1]), "+f"(d[2]), "+f"(d[3])
        : "r"(a[0]), "r"(a[1]), "r"(a[2]), "r"(a[3]), "r"(b0), "r"(b1));
}

// ---------------- init kernels ----------------
__global__ void csr_zero_kernel() {
    int i = blockIdx.x * blockDim.x + threadIdx.x;
    if (i < NN) g_cnt[i] = 0;
    if (i == 0) g_off[0] = 0;
    if (i < NL * 2 * D) ((float*)g_stats)[i] = 0.f;
}

// node_feat (fp32) -> g_hh (fp16)
__global__ void cvt_nf_kernel(const float* __restrict__ nf) {
    int i = blockIdx.x * blockDim.x + threadIdx.x;
    if (i >= NN * D / 4) return;
    float4 v = __ldg((const float4*)nf + i);
    __half2* p = (__half2*)g_hh + i * 2;
    p[0] = __floats2half2_rn(v.x, v.y);
    p[1] = __floats2half2_rn(v.z, v.w);
}

// Pre-split W1/W2 into hi/lo bf16 pairs (smem-image layout)
__global__ void cvt_w_kernel(const float* __restrict__ W1,
                             const float* __restrict__ W2) {
    int i = blockIdx.x * blockDim.x + threadIdx.x;
    if (i >= NL * 64 * 128) return;
    int n = i & 127;
    int kp = (i >> 7) & 63;
    int l = i >> 13;
    int k0 = kp * 2;
    int chunk = k0 >> 4;
    int kpi = (k0 & 15) >> 1;

    {
        float w0 = __ldg(W1 + (size_t)l * D * D + k0 * D + n);
        float w1 = __ldg(W1 + (size_t)l * D * D + (k0 + 1) * D + n);
        float h0 = bf_hi(w0), h1 = bf_hi(w1);
        g_w1p[l][chunk][0][n][kpi] = pack_bf2(h0, h1);
        g_w1p[l][chunk][1][n][kpi] = pack_bf2(w0 - h0, w1 - h1);
    }
    {
        float w0 = __ldg(W2 + (size_t)l * D * D + k0 * D + n);
        float w1 = __ldg(W2 + (size_t)l * D * D + (k0 + 1) * D + n);
        float h0 = bf_hi(w0), h1 = bf_hi(w1);
        g_w2p[l][chunk][0][n][kpi] = pack_bf2(h0, h1);
        g_w2p[l][chunk][1][n][kpi] = pack_bf2(w0 - h0, w1 - h1);
    }
}

// Wout (fp32 [k][n], n=64) -> fp16 smem image
__global__ void cvt_w3_kernel(const float* __restrict__ Wout) {
    int i = blockIdx.x * blockDim.x + threadIdx.x;   // 64 kpairs * 64 n
    if (i >= 64 * 64) return;
    int n = i & 63;
    int kp = i >> 6;
    int k0 = kp * 2;
    int chunk = k0 >> 4;
    int kpi = (k0 & 15) >> 1;
    float w0 = __ldg(Wout + k0 * OD + n);
    float w1 = __ldg(Wout + (k0 + 1) * OD + n);
    g_w3p[chunk][n][kpi] = pack_h2(w0, w1);
}

__global__ void csr_hist_kernel(const int* __restrict__ dst) {
    int i = blockIdx.x * blockDim.x + threadIdx.x;
    if (i >= NE / 4) return;
    int4 d = __ldg((const int4*)dst + i);
    atomicAdd(&g_cnt[d.x], 1);
    atomicAdd(&g_cnt[d.y], 1);
    atomicAdd(&g_cnt[d.z], 1);
    atomicAdd(&g_cnt[d.w], 1);
}

// --- hierarchical scan ---
__global__ void scan1_kernel() {
    int b = blockIdx.x, tid = threadIdx.x;
    int i = b * 256 + tid;
    int v = (i < NN) ? g_cnt[i] : 0;
    int lane = tid & 31, w = tid >> 5;
    int x = v;
#pragma unroll
    for (int o = 1; o < 32; o <<= 1) {
        int t = __shfl_up_sync(0xffffffffu, x, o);
        if (lane >= o) x += t;
    }
    __shared__ int wsum[8];
    if (lane == 31) wsum[w] = x;
    __syncthreads();
    if (w == 0 && lane < 8) {
        int y = wsum[lane];
#pragma unroll
        for (int o = 1; o < 8; o <<= 1) {
            int t = __shfl_up_sync(0xffu, y, o);
            if (lane >= o) y += t;
        }
        wsum[lane] = y;
    }
    __syncthreads();
    int incl = x + (w > 0 ? wsum[w - 1] : 0);
    if (i < NN) {
        g_off[i + 1] = incl;
        g_cur[i] = incl - v;
    }
    if (tid == 255) g_bsum[b] = incl;
}

__global__ void scan2_kernel() {
    int tid = threadIdx.x;
    int lane = tid & 31, w = tid >> 5;
    int v = (tid < NBLK) ? g_bsum[tid] : 0;
    int x = v;
#pragma unroll
    for (int o = 1; o < 32; o <<= 1) {
        int t = __shfl_up_sync(0xffffffffu, x, o);
        if (lane >= o) x += t;
    }
    __shared__ int wsum[8];
    if (lane == 31) wsum[w] = x;
    __syncthreads();
    if (w == 0 && lane < 8) {
        int y = wsum[lane];
#pragma unroll
        for (int o = 1; o < 8; o <<= 1) {
            int t = __shfl_up_sync(0xffu, y, o);
            if (lane >= o) y += t;
        }
        wsum[lane] = y;
    }
    __syncthreads();
    int incl = x + (w > 0 ? wsum[w - 1] : 0);
    if (tid < NBLK) g_bsum[tid] = incl - v;
}

__global__ void scan3_kernel() {
    int b = blockIdx.x;
    int i = b * 256 + threadIdx.x;
    if (i < NN) {
        int base = g_bsum[b];
        g_off[i + 1] += base;
        g_cur[i] += base;
    }
}

__global__ void csr_fill_kernel(const int* __restrict__ src,
                                const int* __restrict__ dst) {
    int i = blockIdx.x * blockDim.x + threadIdx.x;
    if (i >= NE / 4) return;
    int4 s = __ldg((const int4*)src + i);
    int4 d = __ldg((const int4*)dst + i);
    int p0 = atomicAdd(&g_cur[d.x], 1);
    int p1 = atomicAdd(&g_cur[d.y], 1);
    int p2 = atomicAdd(&g_cur[d.z], 1);
    int p3 = atomicAdd(&g_cur[d.w], 1);
    g_csrc[p0] = s.x;
    g_csrc[p1] = s.y;
    g_csrc[p2] = s.z;
    g_csrc[p3] = s.w;
}

// ---------------- gather (fp16 h, 8-deep MLP): xin = (1+eps)h + sum_nbr h ----------------
__global__ void __launch_bounds__(256) gather_kernel(const float* __restrict__ eps,
                                                     int layer) {
    int node = blockIdx.x * 8 + (threadIdx.x >> 5);
    if (node >= NN) return;
    int lane = threadIdx.x & 31;
    float oe = 1.0f + __ldg(eps + layer);

    int beg = g_off[node];
    int end = g_off[node + 1];

    const __half* hb = g_hh;
    float4 hv = h4_to_f4(*(const uint2*)(hb + (size_t)node * D + lane * 4));
    float4 acc;
    acc.x = oe * hv.x; acc.y = oe * hv.y; acc.z = oe * hv.z; acc.w = oe * hv.w;

    int i = beg;
    for (; i + 7 < end; i += 8) {
        uint2 u[8];
#pragma unroll
        for (int j = 0; j < 8; j++) {
            int s = __ldg(g_csrc + i + j);
            u[j] = *(const uint2*)(hb + (size_t)s * D + lane * 4);
        }
#pragma unroll
        for (int j = 0; j < 8; j++) {
            float4 v = h4_to_f4(u[j]);
            acc.x += v.x; acc.y += v.y; acc.z += v.z; acc.w += v.w;
        }
    }
    for (; i + 3 < end; i += 4) {
        uint2 u[4];
#pragma unroll
        for (int j = 0; j < 4; j++) {
            int s = __ldg(g_csrc + i + j);
            u[j] = *(const uint2*)(hb + (size_t)s * D + lane * 4);
        }
#pragma unroll
        for (int j = 0; j < 4; j++) {
            float4 v = h4_to_f4(u[j]);
            acc.x += v.x; acc.y += v.y; acc.z += v.z; acc.w += v.w;
        }
    }
    for (; i < end; i++) {
        int s = __ldg(g_csrc + i);
        float4 v = h4_to_f4(*(const uint2*)(hb + (size_t)s * D + lane * 4));
        acc.x += v.x; acc.y += v.y; acc.z += v.z; acc.w += v.w;
    }
    *(float4*)(g_xin + (size_t)node * D + lane * 4) = acc;
}

// =====================================================================
// Split-bf16 tensor-core GEMM core.
// =====================================================================

struct SmemGemm {
    unsigned A[2][2][64 * 8];    // [buf][hi/lo][m*8 + kpair]
    unsigned B[2][2][128 * 8];   // [buf][hi/lo][n*8 + kpair]
};

__device__ __forceinline__ void split4(float4 v, unsigned* hi, unsigned* lo) {
    float h0 = bf_hi(v.x), h1 = bf_hi(v.y), h2 = bf_hi(v.z), h3 = bf_hi(v.w);
    hi[0] = pack_bf2(h0, h1);
    hi[1] = pack_bf2(h2, h3);
    lo[0] = pack_bf2(v.x - h0, v.y - h1);
    lo[1] = pack_bf2(v.z - h2, v.w - h3);
}

// ---------------- GEMM1: x = xin @ W1 + b1, + BN stats ----------------
__global__ void __launch_bounds__(256) gemm1_tc_kernel(const float* __restrict__ b1,
                                                       int layer) {
    __shared__ SmemGemm sm;
    __shared__ float SredS[128], SredQ[128];

    int tid = threadIdx.x;
    int lane = tid & 31;
    int wid = tid >> 5;
    int wm = wid & 3;
    int wn = wid >> 2;
    int m0 = blockIdx.x * 64;

    if (tid < 128) { SredS[tid] = 0.f; SredQ[tid] = 0.f; }

    int lm = tid >> 2;
    int lq = (tid & 3);
    int gm_ld = m0 + lm;
    const unsigned* Wc = &g_w1p[layer][0][0][0][0];

    // prologue: chunk 0
    {
        float4 v = make_float4(0.f, 0.f, 0.f, 0.f);
        if (gm_ld < NN) v = *(const float4*)(g_xin + (size_t)gm_ld * D + lq * 4);
        unsigned hi[2], lo[2];
        split4(v, hi, lo);
        sm.A[0][0][lm * 8 + lq * 2] = hi[0];
        sm.A[0][0][lm * 8 + lq * 2 + 1] = hi[1];
        sm.A[0][1][lm * 8 + lq * 2] = lo[0];
        sm.A[0][1][lm * 8 + lq * 2 + 1] = lo[1];
        const uint4* Wg = (const uint4*)Wc;
        uint4 wh = Wg[tid], wl = Wg[tid + 256];
        ((uint4*)sm.B[0][0])[tid] = wh;
        ((uint4*)sm.B[0][1])[tid] = wl;
    }
    __syncthreads();

    float d[8][4];
#pragma unroll
    for (int nt = 0; nt < 8; nt++)
#pragma unroll
        for (int c = 0; c < 4; c++) d[nt][c] = 0.f;

    int kq = lane & 3;
    int gr = lane >> 2;
    int ca = wm * 16 + gr;

#pragma unroll
    for (int kk = 0; kk < 8; kk++) {
        const int cur = kk & 1;
        unsigned nah[2], nal[2];
        uint4 nwh, nwl;
        if (kk < 7) {
            float4 v = make_float4(0.f, 0.f, 0.f, 0.f);
            if (gm_ld < NN)
                v = *(const float4*)(g_xin + (size_t)gm_ld * D + (kk + 1) * 16 + lq * 4);
            split4(v, nah, nal);
            const uint4* Wg = (const uint4*)(Wc + (kk + 1) * 2048);
            nwh = Wg[tid]; nwl = Wg[tid + 256];
        }
        unsigned ah[4], al[4];
        ah[0] = sm.A[cur][0][ca * 8 + kq];
        ah[1] = sm.A[cur][0][(ca + 8) * 8 + kq];
        ah[2] = sm.A[cur][0][ca * 8 + kq + 4];
        ah[3] = sm.A[cur][0][(ca + 8) * 8 + kq + 4];
        al[0] = sm.A[cur][1][ca * 8 + kq];
        al[1] = sm.A[cur][1][(ca + 8) * 8 + kq];
        al[2] = sm.A[cur][1][ca * 8 + kq + 4];
        al[3] = sm.A[cur][1][(ca + 8) * 8 + kq + 4];
#pragma unroll
        for (int nt = 0; nt < 8; nt++) {
            int cb = wn * 64 + nt * 8 + gr;
            unsigned bh0 = sm.B[cur][0][cb * 8 + kq];
            unsigned bh1 = sm.B[cur][0][cb * 8 + kq + 4];
            unsigned bl0 = sm.B[cur][1][cb * 8 + kq];
            unsigned bl1 = sm.B[cur][1][cb * 8 + kq + 4];
            mma_bf16(d[nt], ah, bh0, bh1);
            mma_bf16(d[nt], ah, bl0, bl1);
            mma_bf16(d[nt], al, bh0, bh1);
        }
        if (kk < 7) {
            const int nxt = cur ^ 1;
            sm.A[nxt][0][lm * 8 + lq * 2] = nah[0];
            sm.A[nxt][0][lm * 8 + lq * 2 + 1] = nah[1];
            sm.A[nxt][1][lm * 8 + lq * 2] = nal[0];
            sm.A[nxt][1][lm * 8 + lq * 2 + 1] = nal[1];
            ((uint4*)sm.B[nxt][0])[tid] = nwh;
            ((uint4*)sm.B[nxt][1])[tid] = nwl;
            __syncthreads();
        }
    }

    // epilogue: bias, store x, BN stats
    int r0 = m0 + wm * 16 + gr;
    int r1 = r0 + 8;
    bool v0r = (r0 < NN), v1r = (r1 < NN);
#pragma unroll
    for (int nt = 0; nt < 8; nt++) {
        int c0 = wn * 64 + nt * 8 + 2 * kq;
        float bb0 = __ldg(b1 + (size_t)layer * D + c0);
        float bb1 = __ldg(b1 + (size_t)layer * D + c0 + 1);
        float x0 = d[nt][0] + bb0, x1 = d[nt][1] + bb1;
        float x2 = d[nt][2] + bb0, x3 = d[nt][3] + bb1;
        if (v0r) *(float2*)(g_x + (size_t)r0 * D + c0) = make_float2(x0, x1);
        if (v1r) *(float2*)(g_x + (size_t)r1 * D + c0) = make_float2(x2, x3);
        float sc0 = (v0r ? x0 : 0.f) + (v1r ? x2 : 0.f);
        float sc1 = (v0r ? x1 : 0.f) + (v1r ? x3 : 0.f);
        float qc0 = (v0r ? x0 * x0 : 0.f) + (v1r ? x2 * x2 : 0.f);
        float qc1 = (v0r ? x1 * x1 : 0.f) + (v1r ? x3 * x3 : 0.f);
#pragma unroll
        for (int o = 4; o <= 16; o <<= 1) {
            sc0 += __shfl_xor_sync(0xffffffffu, sc0, o);
            sc1 += __shfl_xor_sync(0xffffffffu, sc1, o);
            qc0 += __shfl_xor_sync(0xffffffffu, qc0, o);
            qc1 += __shfl_xor_sync(0xffffffffu, qc1, o);
        }
        if (gr == 0) {
            atomicAdd(&SredS[c0], sc0);
            atomicAdd(&SredS[c0 + 1], sc1);
            atomicAdd(&SredQ[c0], qc0);
            atomicAdd(&SredQ[c0 + 1], qc1);
        }
    }
    __syncthreads();
    if (tid < 128) {
        atomicAdd(&g_stats[layer][tid], SredS[tid]);
        atomicAdd(&g_stats[layer][D + tid], SredQ[tid]);
    }
}

// ---------------- GEMM2: h = relu( relu(BN(x)) @ W2 + b2 ) -> fp16 g_hh ----------------
__global__ void __launch_bounds__(256) gemm2_tc_kernel(const float* __restrict__ b2,
                                                       const float* __restrict__ gamma,
                                                       const float* __restrict__ beta,
                                                       int layer) {
    __shared__ SmemGemm sm;
    __shared__ float s_sc[128], s_sh[128];

    int tid = threadIdx.x;
    int lane = tid & 31;
    int wid = tid >> 5;
    int wm = wid & 3;
    int wn = wid >> 2;
    int m0 = blockIdx.x * 64;

    if (tid < 128) {
        float inv = 1.0f / (float)NN;
        float mu = g_stats[layer][tid] * inv;
        float var = g_stats[layer][D + tid] * inv - mu * mu;
        float rs = rsqrtf(var + 1e-5f);
        float sc = rs * __ldg(gamma + (size_t)layer * D + tid);
        s_sc[tid] = sc;
        s_sh[tid] = __ldg(beta + (size_t)layer * D + tid) - mu * sc;
    }
    __syncthreads();

    int lm = tid >> 2;
    int lq = (tid & 3);
    int gm_ld = m0 + lm;
    const unsigned* Wc = &g_w2p[layer][0][0][0][0];

    // prologue chunk 0: A = relu(BN(x)) split
    {
        float4 v = make_float4(0.f, 0.f, 0.f, 0.f);
        if (gm_ld < NN) {
            float4 xv = *(const float4*)(g_x + (size_t)gm_ld * D + lq * 4);
            int c = lq * 4;
            v.x = fmaxf(fmaf(xv.x, s_sc[c + 0], s_sh[c + 0]), 0.f);
            v.y = fmaxf(fmaf(xv.y, s_sc[c + 1], s_sh[c + 1]), 0.f);
            v.z = fmaxf(fmaf(xv.z, s_sc[c + 2], s_sh[c + 2]), 0.f);
            v.w = fmaxf(fmaf(xv.w, s_sc[c + 3], s_sh[c + 3]), 0.f);
        }
        unsigned hi[2], lo[2];
        split4(v, hi, lo);
        sm.A[0][0][lm * 8 + lq * 2] = hi[0];
        sm.A[0][0][lm * 8 + lq * 2 + 1] = hi[1];
        sm.A[0][1][lm * 8 + lq * 2] = lo[0];
        sm.A[0][1][lm * 8 + lq * 2 + 1] = lo[1];
        const uint4* Wg = (const uint4*)Wc;
        uint4 wh = Wg[tid], wl = Wg[tid + 256];
        ((uint4*)sm.B[0][0])[tid] = wh;
        ((uint4*)sm.B[0][1])[tid] = wl;
    }
    __syncthreads();

    float d[8][4];
#pragma unroll
    for (int nt = 0; nt < 8; nt++)
#pragma unroll
        for (int c = 0; c < 4; c++) d[nt][c] = 0.f;

    int kq = lane & 3;
    int gr = lane >> 2;
    int ca = wm * 16 + gr;

#pragma unroll
    for (int kk = 0; kk < 8; kk++) {
        const int cur = kk & 1;
        unsigned nah[2], nal[2];
        uint4 nwh, nwl;
        if (kk < 7) {
            float4 v = make_float4(0.f, 0.f, 0.f, 0.f);
            int kc = (kk + 1) * 16;
            if (gm_ld < NN) {
                float4 xv = *(const float4*)(g_x + (size_t)gm_ld * D + kc + lq * 4);
                int c = kc + lq * 4;
                v.x = fmaxf(fmaf(xv.x, s_sc[c + 0], s_sh[c + 0]), 0.f);
                v.y = fmaxf(fmaf(xv.y, s_sc[c + 1], s_sh[c + 1]), 0.f);
                v.z = fmaxf(fmaf(xv.z, s_sc[c + 2], s_sh[c + 2]), 0.f);
                v.w = fmaxf(fmaf(xv.w, s_sc[c + 3], s_sh[c + 3]), 0.f);
            }
            split4(v, nah, nal);
            const uint4* Wg = (const uint4*)(Wc + (kk + 1) * 2048);
            nwh = Wg[tid]; nwl = Wg[tid + 256];
        }
        unsigned ah[4], al[4];
        ah[0] = sm.A[cur][0][ca * 8 + kq];
        ah[1] = sm.A[cur][0][(ca + 8) * 8 + kq];
        ah[2] = sm.A[cur][0][ca * 8 + kq + 4];
        ah[3] = sm.A[cur][0][(ca + 8) * 8 + kq + 4];
        al[0] = sm.A[cur][1][ca * 8 + kq];
        al[1] = sm.A[cur][1][(ca + 8) * 8 + kq];
        al[2] = sm.A[cur][1][ca * 8 + kq + 4];
        al[3] = sm.A[cur][1][(ca + 8) * 8 + kq + 4];
#pragma unroll
        for (int nt = 0; nt < 8; nt++) {
            int cb = wn * 64 + nt * 8 + gr;
            unsigned bh0 = sm.B[cur][0][cb * 8 + kq];
            unsigned bh1 = sm.B[cur][0][cb * 8 + kq + 4];
            unsigned bl0 = sm.B[cur][1][cb * 8 + kq];
            unsigned bl1 = sm.B[cur][1][cb * 8 + kq + 4];
            mma_bf16(d[nt], ah, bh0, bh1);
            mma_bf16(d[nt], ah, bl0, bl1);
            mma_bf16(d[nt], al, bh0, bh1);
        }
        if (kk < 7) {
            const int nxt = cur ^ 1;
            sm.A[nxt][0][lm * 8 + lq * 2] = nah[0];
            sm.A[nxt][0][lm * 8 + lq * 2 + 1] = nah[1];
            sm.A[nxt][1][lm * 8 + lq * 2] = nal[0];
            sm.A[nxt][1][lm * 8 + lq * 2 + 1] = nal[1];
            ((uint4*)sm.B[nxt][0])[tid] = nwh;
            ((uint4*)sm.B[nxt][1])[tid] = nwl;
            __syncthreads();
        }
    }

    // epilogue: relu(d + b2) -> g_hh (fp16)
    int r0 = m0 + wm * 16 + gr;
    int r1 = r0 + 8;
#pragma unroll
    for (int nt = 0; nt < 8; nt++) {
        int c0 = wn * 64 + nt * 8 + 2 * kq;
        float bb0 = __ldg(b2 + (size_t)layer * D + c0);
        float bb1 = __ldg(b2 + (size_t)layer * D + c0 + 1);
        if (r0 < NN) {
            *(__half2*)(g_hh + (size_t)r0 * D + c0) =
                __floats2half2_rn(fmaxf(d[nt][0] + bb0, 0.f),
                                  fmaxf(d[nt][1] + bb1, 0.f));
        }
        if (r1 < NN) {
            *(__half2*)(g_hh + (size_t)r1 * D + c0) =
                __floats2half2_rn(fmaxf(d[nt][2] + bb0, 0.f),
                                  fmaxf(d[nt][3] + bb1, 0.f));
        }
    }
}

// ---------------- GEMM3 (fp16 tensor core): out = h @ Wout + bout ----------------
// BM=64, BN=64, 256 thr = 8 warps (4m x 2n), warp tile 16x32 (4 n-tiles).
__global__ void __launch_bounds__(256) gemm3_tc_kernel(const float* __restrict__ bout,
                                                       float* __restrict__ out) {
    __shared__ unsigned sA[64 * 8];   // [m][kpair] fp16 pairs
    __shared__ unsigned sB[64 * 8];   // [n][kpair]

    int tid = threadIdx.x;
    int lane = tid & 31;
    int wid = tid >> 5;
    int wm = wid & 3;
    int wn = wid >> 2;
    int m0 = blockIdx.x * 64;

    int lm = tid >> 2;
    int lq = tid & 3;
    int gm_ld = m0 + lm;

    float d[4][4];
#pragma unroll
    for (int nt = 0; nt < 4; nt++)
#pragma unroll
        for (int c = 0; c < 4; c++) d[nt][c] = 0.f;

    int kq = lane & 3;
    int gr = lane >> 2;
    int ca = wm * 16 + gr;

#pragma unroll
    for (int kk = 0; kk < 8; kk++) {
        // load A chunk: fp16 rows direct from g_hh
        uint2 a2 = make_uint2(0u, 0u);
        if (gm_ld < NN)
            a2 = *(const uint2*)(g_hh + (size_t)gm_ld * D + kk * 16 + lq * 4);
        sA[lm * 8 + lq * 2] = a2.x;
        sA[lm * 8 + lq * 2 + 1] = a2.y;
        // load B chunk: 512 uints via 128 threads x uint4
        if (tid < 128)
            ((uint4*)sB)[tid] = ((const uint4*)&g_w3p[kk][0][0])[tid];
        __syncthreads();

        unsigned a[4];
        a[0] = sA[ca * 8 + kq];
        a[1] = sA[(ca + 8) * 8 + kq];
        a[2] = sA[ca * 8 + kq + 4];
        a[3] = sA[(ca + 8) * 8 + kq + 4];
#pragma unroll
        for (int nt = 0; nt < 4; nt++) {
            int cb = wn * 32 + nt * 8 + gr;
            unsigned b0 = sB[cb * 8 + kq];
            unsigned b1 = sB[cb * 8 + kq + 4];
            mma_f16(d[nt], a, b0, b1);
        }
        __syncthreads();
    }

    int r0 = m0 + wm * 16 + gr;
    int r1 = r0 + 8;
#pragma unroll
    for (int nt = 0; nt < 4; nt++) {
        int c0 = wn * 32 + nt * 8 + 2 * kq;
        float bb0 = __ldg(bout + c0);
        float bb1 = __ldg(bout + c0 + 1);
        if (r0 < NN)
            *(float2*)(out + (size_t)r0 * OD + c0) =
                make_float2(d[nt][0] + bb0, d[nt][1] + bb1);
        if (r1 < NN)
            *(float2*)(out + (size_t)r1 * OD + c0) =
                make_float2(d[nt][2] + bb0, d[nt][3] + bb1);
    }
}

// ---------------- launch ----------------
extern "C" void kernel_launch(void* const* d_in, const int* in_sizes, int n_in,
                              void* d_out, int out_size) {
    const float* node_feat = (const float*)d_in[0];
    const int*   src       = (const int*)d_in[1];
    const int*   dst       = (const int*)d_in[2];
    const float* W1        = (const float*)d_in[3];
    const float* b1        = (const float*)d_in[4];
    const float* gamma     = (const float*)d_in[5];
    const float* beta      = (const float*)d_in[6];
    const float* W2        = (const float*)d_in[7];
    const float* b2        = (const float*)d_in[8];
    const float* eps       = (const float*)d_in[9];
    const float* Wout      = (const float*)d_in[10];
    const float* bout      = (const float*)d_in[11];
    float* out = (float*)d_out;

    const int gemm_grid  = (NN + 63) / 64;          // 782
    const int edge4_grid = (NE / 4 + 255) / 256;    // 1563
    const int node_grid  = (NN + 255) / 256;        // 196
    const int gath_grid  = (NN + 7) / 8;            // 6250
    const int cvtw_grid  = (NL * 64 * 128 + 255) / 256;
    const int cvtn_grid  = (NN * D / 4 + 255) / 256;

    csr_zero_kernel<<<node_grid, 256>>>();
    cvt_nf_kernel<<<cvtn_grid, 256>>>(node_feat);
    cvt_w_kernel<<<cvtw_grid, 256>>>(W1, W2);
    cvt_w3_kernel<<<16, 256>>>(Wout);
    csr_hist_kernel<<<edge4_grid, 256>>>(dst);
    scan1_kernel<<<NBLK, 256>>>();
    scan2_kernel<<<1, 256>>>();
    scan3_kernel<<<NBLK, 256>>>();
    csr_fill_kernel<<<edge4_grid, 256>>>(src, dst);

    for (int l = 0; l < NL; l++) {
        gather_kernel<<<gath_grid, 256>>>(eps, l);
        gemm1_tc_kernel<<<gemm_grid, 256>>>(b1, l);
        gemm2_tc_kernel<<<gemm_grid, 256>>>(b2, gamma, beta, l);
    }
    gemm3_tc_kernel<<<gemm_grid, 256>>>(bout, out);
}

// round 11
// speedup vs baseline: 2.8460x; 1.0262x over previous
#include <cuda_runtime.h>
#include <cuda_bf16.h>
#include <cuda_fp16.h>

#define NN 50000
#define NE 1600000
#define D  128
#define OD 64
#define NL 3
#define NBLK 196   // ceil(NN/256)

// ---------------- device scratch ----------------
__device__ __half g_hh[NN * D];        // node features (fp16) — gather/gemm3 input
__device__ float g_x[NN * D];          // MLP hidden pre-BN (fp32)
__device__ float g_xin[NN * D];        // (1+eps)h + agg (fp32)
__device__ float g_stats[NL][2 * D];   // per-layer per-channel sum & sumsq

// Pre-split weights, smem image layout:
// [layer][chunk(8)][hi/lo(2)][n(128)][kpair(8)]  (each uint = 2 bf16, low = even k)
__device__ unsigned g_w1p[NL][8][2][128][8];
__device__ unsigned g_w2p[NL][8][2][128][8];
// Wout in fp16, smem image: [chunk(8)][n(64)][kpair(8)] (uint = 2 fp16)
__device__ unsigned g_w3p[8][64][8];

// CSR (dual-bucket counters/cursors to halve atomic contention)
__device__ int g_cnt[2][NN];
__device__ int g_cur[2][NN];
__device__ int g_off[NN + 1];
__device__ int g_csrc[NE];
__device__ int g_bsum[NBLK + 1];

__device__ __forceinline__ unsigned pack_bf2(float a, float b) {
    __nv_bfloat162 t = __floats2bfloat162_rn(a, b);
    return *reinterpret_cast<unsigned*>(&t);
}
__device__ __forceinline__ unsigned pack_h2(float a, float b) {
    __half2 t = __floats2half2_rn(a, b);
    return *reinterpret_cast<unsigned*>(&t);
}
__device__ __forceinline__ float bf_hi(float x) {
    return __bfloat162float(__float2bfloat16_rn(x));
}
__device__ __forceinline__ float4 h4_to_f4(uint2 u) {
    __half2 a = *reinterpret_cast<__half2*>(&u.x);
    __half2 b = *reinterpret_cast<__half2*>(&u.y);
    float2 fa = __half22float2(a), fb = __half22float2(b);
    return make_float4(fa.x, fa.y, fb.x, fb.y);
}

__device__ __forceinline__ void mma_bf16(float* d, const unsigned* a,
                                         unsigned b0, unsigned b1) {
    asm volatile(
        "mma.sync.aligned.m16n8k16.row.col.f32.bf16.bf16.f32 "
        "{%0,%1,%2,%3}, {%4,%5,%6,%7}, {%8,%9}, {%0,%1,%2,%3};"
        : "+f"(d[0]), "+f"(d[1]), "+f"(d[2]), "+f"(d[3])
        : "r"(a[0]), "r"(a[1]), "r"(a[2]), "r"(a[3]), "r"(b0), "r"(b1));
}
__device__ __forceinline__ void mma_f16(float* d, const unsigned* a,
                                        unsigned b0, unsigned b1) {
    asm volatile(
        "mma.sync.aligned.m16n8k16.row.col.f32.f16.f16.f32 "
        "{%0,%1,%2,%3}, {%4,%5,%6,%7}, {%8,%9}, {%0,%1,%2,%3};"
        : "+f"(d[0]), "+f"(d[1]), "+f"(d[2]), "+f"(d[3])
        : "r"(a[0]), "r"(a[1]), "r"(a[2]), "r"(a[3]), "r"(b0), "r"(b1));
}

// ---------------- fused init: cvt_nf + csr_zero + cvt_w + cvt_w3 + stats ----------------
#define R_NF   (NN * D / 4)          // 1,600,000
#define R_W    (NL * 64 * 128)       // 24,576
#define R_W3   (64 * 64)             // 4,096
#define R_ST   (NL * 2 * D)          // 768
#define R_TOT  (R_NF + NN + R_W + R_W3 + R_ST)

__global__ void init_kernel(const float* __restrict__ nf,
                            const float* __restrict__ W1,
                            const float* __restrict__ W2,
                            const float* __restrict__ Wout) {
    int i = blockIdx.x * blockDim.x + threadIdx.x;
    if (i < R_NF) {
        // node_feat fp32 -> fp16
        float4 v = __ldg((const float4*)nf + i);
        __half2* p = (__half2*)g_hh + i * 2;
        p[0] = __floats2half2_rn(v.x, v.y);
        p[1] = __floats2half2_rn(v.z, v.w);
        return;
    }
    int r = i - R_NF;
    if (r < NN) {
        g_cnt[0][r] = 0;
        g_cnt[1][r] = 0;
        if (r == 0) g_off[0] = 0;
        return;
    }
    r -= NN;
    if (r < R_W) {
        int n = r & 127;
        int kp = (r >> 7) & 63;
        int l = r >> 13;
        int k0 = kp * 2;
        int chunk = k0 >> 4;
        int kpi = (k0 & 15) >> 1;
        {
            float w0 = __ldg(W1 + (size_t)l * D * D + k0 * D + n);
            float w1 = __ldg(W1 + (size_t)l * D * D + (k0 + 1) * D + n);
            float h0 = bf_hi(w0), h1 = bf_hi(w1);
            g_w1p[l][chunk][0][n][kpi] = pack_bf2(h0, h1);
            g_w1p[l][chunk][1][n][kpi] = pack_bf2(w0 - h0, w1 - h1);
        }
        {
            float w0 = __ldg(W2 + (size_t)l * D * D + k0 * D + n);
            float w1 = __ldg(W2 + (size_t)l * D * D + (k0 + 1) * D + n);
            float h0 = bf_hi(w0), h1 = bf_hi(w1);
            g_w2p[l][chunk][0][n][kpi] = pack_bf2(h0, h1);
            g_w2p[l][chunk][1][n][kpi] = pack_bf2(w0 - h0, w1 - h1);
        }
        return;
    }
    r -= R_W;
    if (r < R_W3) {
        int n = r & 63;
        int kp = r >> 6;
        int k0 = kp * 2;
        int chunk = k0 >> 4;
        int kpi = (k0 & 15) >> 1;
        float w0 = __ldg(Wout + k0 * OD + n);
        float w1 = __ldg(Wout + (k0 + 1) * OD + n);
        g_w3p[chunk][n][kpi] = pack_h2(w0, w1);
        return;
    }
    r -= R_W3;
    if (r < R_ST) ((float*)g_stats)[r] = 0.f;
}

// ---------------- CSR build (dual-bucket) ----------------
__global__ void csr_hist_kernel(const int* __restrict__ dst) {
    int i = blockIdx.x * blockDim.x + threadIdx.x;
    if (i >= NE / 4) return;
    int b = (i < NE / 8) ? 0 : 1;
    int4 d = __ldg((const int4*)dst + i);
    atomicAdd(&g_cnt[b][d.x], 1);
    atomicAdd(&g_cnt[b][d.y], 1);
    atomicAdd(&g_cnt[b][d.z], 1);
    atomicAdd(&g_cnt[b][d.w], 1);
}

// --- hierarchical scan ---
__global__ void scan1_kernel() {
    int b = blockIdx.x, tid = threadIdx.x;
    int i = b * 256 + tid;
    int c0 = (i < NN) ? g_cnt[0][i] : 0;
    int c1 = (i < NN) ? g_cnt[1][i] : 0;
    int v = c0 + c1;
    int lane = tid & 31, w = tid >> 5;
    int x = v;
#pragma unroll
    for (int o = 1; o < 32; o <<= 1) {
        int t = __shfl_up_sync(0xffffffffu, x, o);
        if (lane >= o) x += t;
    }
    __shared__ int wsum[8];
    if (lane == 31) wsum[w] = x;
    __syncthreads();
    if (w == 0 && lane < 8) {
        int y = wsum[lane];
#pragma unroll
        for (int o = 1; o < 8; o <<= 1) {
            int t = __shfl_up_sync(0xffu, y, o);
            if (lane >= o) y += t;
        }
        wsum[lane] = y;
    }
    __syncthreads();
    int incl = x + (w > 0 ? wsum[w - 1] : 0);
    if (i < NN) {
        g_off[i + 1] = incl;
        g_cur[0][i] = incl - v;          // bucket-0 cursor (local; base added in scan3)
        g_cur[1][i] = incl - v + c0;     // bucket-1 starts after bucket-0's slots
    }
    if (tid == 255) g_bsum[b] = incl;
}

__global__ void scan2_kernel() {
    int tid = threadIdx.x;
    int lane = tid & 31, w = tid >> 5;
    int v = (tid < NBLK) ? g_bsum[tid] : 0;
    int x = v;
#pragma unroll
    for (int o = 1; o < 32; o <<= 1) {
        int t = __shfl_up_sync(0xffffffffu, x, o);
        if (lane >= o) x += t;
    }
    __shared__ int wsum[8];
    if (lane == 31) wsum[w] = x;
    __syncthreads();
    if (w == 0 && lane < 8) {
        int y = wsum[lane];
#pragma unroll
        for (int o = 1; o < 8; o <<= 1) {
            int t = __shfl_up_sync(0xffu, y, o);
            if (lane >= o) y += t;
        }
        wsum[lane] = y;
    }
    __syncthreads();
    int incl = x + (w > 0 ? wsum[w - 1] : 0);
    if (tid < NBLK) g_bsum[tid] = incl - v;
}

__global__ void scan3_kernel() {
    int b = blockIdx.x;
    int i = b * 256 + threadIdx.x;
    if (i < NN) {
        int base = g_bsum[b];
        g_off[i + 1] += base;
        g_cur[0][i] += base;
        g_cur[1][i] += base;
    }
}

__global__ void csr_fill_kernel(const int* __restrict__ src,
                                const int* __restrict__ dst) {
    int i = blockIdx.x * blockDim.x + threadIdx.x;
    if (i >= NE / 4) return;
    int b = (i < NE / 8) ? 0 : 1;
    int4 s = __ldg((const int4*)src + i);
    int4 d = __ldg((const int4*)dst + i);
    int p0 = atomicAdd(&g_cur[b][d.x], 1);
    int p1 = atomicAdd(&g_cur[b][d.y], 1);
    int p2 = atomicAdd(&g_cur[b][d.z], 1);
    int p3 = atomicAdd(&g_cur[b][d.w], 1);
    g_csrc[p0] = s.x;
    g_csrc[p1] = s.y;
    g_csrc[p2] = s.z;
    g_csrc[p3] = s.w;
}

// ---------------- gather (fp16 h, 8-deep MLP): xin = (1+eps)h + sum_nbr h ----------------
__global__ void __launch_bounds__(256) gather_kernel(const float* __restrict__ eps,
                                                     int layer) {
    int node = blockIdx.x * 8 + (threadIdx.x >> 5);
    if (node >= NN) return;
    int lane = threadIdx.x & 31;
    float oe = 1.0f + __ldg(eps + layer);

    int beg = g_off[node];
    int end = g_off[node + 1];

    const __half* hb = g_hh;
    float4 hv = h4_to_f4(*(const uint2*)(hb + (size_t)node * D + lane * 4));
    float4 acc;
    acc.x = oe * hv.x; acc.y = oe * hv.y; acc.z = oe * hv.z; acc.w = oe * hv.w;

    int i = beg;
    for (; i + 7 < end; i += 8) {
        uint2 u[8];
#pragma unroll
        for (int j = 0; j < 8; j++) {
            int s = __ldg(g_csrc + i + j);
            u[j] = *(const uint2*)(hb + (size_t)s * D + lane * 4);
        }
#pragma unroll
        for (int j = 0; j < 8; j++) {
            float4 v = h4_to_f4(u[j]);
            acc.x += v.x; acc.y += v.y; acc.z += v.z; acc.w += v.w;
        }
    }
    for (; i + 3 < end; i += 4) {
        uint2 u[4];
#pragma unroll
        for (int j = 0; j < 4; j++) {
            int s = __ldg(g_csrc + i + j);
            u[j] = *(const uint2*)(hb + (size_t)s * D + lane * 4);
        }
#pragma unroll
        for (int j = 0; j < 4; j++) {
            float4 v = h4_to_f4(u[j]);
            acc.x += v.x; acc.y += v.y; acc.z += v.z; acc.w += v.w;
        }
    }
    for (; i < end; i++) {
        int s = __ldg(g_csrc + i);
        float4 v = h4_to_f4(*(const uint2*)(hb + (size_t)s * D + lane * 4));
        acc.x += v.x; acc.y += v.y; acc.z += v.z; acc.w += v.w;
    }
    *(float4*)(g_xin + (size_t)node * D + lane * 4) = acc;
}

// =====================================================================
// Split-bf16 tensor-core GEMM core.
// =====================================================================

struct SmemGemm {
    unsigned A[2][2][64 * 8];    // [buf][hi/lo][m*8 + kpair]
    unsigned B[2][2][128 * 8];   // [buf][hi/lo][n*8 + kpair]
};

__device__ __forceinline__ void split4(float4 v, unsigned* hi, unsigned* lo) {
    float h0 = bf_hi(v.x), h1 = bf_hi(v.y), h2 = bf_hi(v.z), h3 = bf_hi(v.w);
    hi[0] = pack_bf2(h0, h1);
    hi[1] = pack_bf2(h2, h3);
    lo[0] = pack_bf2(v.x - h0, v.y - h1);
    lo[1] = pack_bf2(v.z - h2, v.w - h3);
}

// ---------------- GEMM1: x = xin @ W1 + b1, + BN stats ----------------
__global__ void __launch_bounds__(256) gemm1_tc_kernel(const float* __restrict__ b1,
                                                       int layer) {
    __shared__ SmemGemm sm;
    __shared__ float SredS[128], SredQ[128];

    int tid = threadIdx.x;
    int lane = tid & 31;
    int wid = tid >> 5;
    int wm = wid & 3;
    int wn = wid >> 2;
    int m0 = blockIdx.x * 64;

    if (tid < 128) { SredS[tid] = 0.f; SredQ[tid] = 0.f; }

    int lm = tid >> 2;
    int lq = (tid & 3);
    int gm_ld = m0 + lm;
    const unsigned* Wc = &g_w1p[layer][0][0][0][0];

    // prologue: chunk 0
    {
        float4 v = make_float4(0.f, 0.f, 0.f, 0.f);
        if (gm_ld < NN) v = *(const float4*)(g_xin + (size_t)gm_ld * D + lq * 4);
        unsigned hi[2], lo[2];
        split4(v, hi, lo);
        sm.A[0][0][lm * 8 + lq * 2] = hi[0];
        sm.A[0][0][lm * 8 + lq * 2 + 1] = hi[1];
        sm.A[0][1][lm * 8 + lq * 2] = lo[0];
        sm.A[0][1][lm * 8 + lq * 2 + 1] = lo[1];
        const uint4* Wg = (const uint4*)Wc;
        uint4 wh = Wg[tid], wl = Wg[tid + 256];
        ((uint4*)sm.B[0][0])[tid] = wh;
        ((uint4*)sm.B[0][1])[tid] = wl;
    }
    __syncthreads();

    float d[8][4];
#pragma unroll
    for (int nt = 0; nt < 8; nt++)
#pragma unroll
        for (int c = 0; c < 4; c++) d[nt][c] = 0.f;

    int kq = lane & 3;
    int gr = lane >> 2;
    int ca = wm * 16 + gr;

#pragma unroll
    for (int kk = 0; kk < 8; kk++) {
        const int cur = kk & 1;
        unsigned nah[2], nal[2];
        uint4 nwh, nwl;
        if (kk < 7) {
            float4 v = make_float4(0.f, 0.f, 0.f, 0.f);
            if (gm_ld < NN)
                v = *(const float4*)(g_xin + (size_t)gm_ld * D + (kk + 1) * 16 + lq * 4);
            split4(v, nah, nal);
            const uint4* Wg = (const uint4*)(Wc + (kk + 1) * 2048);
            nwh = Wg[tid]; nwl = Wg[tid + 256];
        }
        unsigned ah[4], al[4];
        ah[0] = sm.A[cur][0][ca * 8 + kq];
        ah[1] = sm.A[cur][0][(ca + 8) * 8 + kq];
        ah[2] = sm.A[cur][0][ca * 8 + kq + 4];
        ah[3] = sm.A[cur][0][(ca + 8) * 8 + kq + 4];
        al[0] = sm.A[cur][1][ca * 8 + kq];
        al[1] = sm.A[cur][1][(ca + 8) * 8 + kq];
        al[2] = sm.A[cur][1][ca * 8 + kq + 4];
        al[3] = sm.A[cur][1][(ca + 8) * 8 + kq + 4];
#pragma unroll
        for (int nt = 0; nt < 8; nt++) {
            int cb = wn * 64 + nt * 8 + gr;
            unsigned bh0 = sm.B[cur][0][cb * 8 + kq];
            unsigned bh1 = sm.B[cur][0][cb * 8 + kq + 4];
            unsigned bl0 = sm.B[cur][1][cb * 8 + kq];
            unsigned bl1 = sm.B[cur][1][cb * 8 + kq + 4];
            mma_bf16(d[nt], ah, bh0, bh1);
            mma_bf16(d[nt], ah, bl0, bl1);
            mma_bf16(d[nt], al, bh0, bh1);
        }
        if (kk < 7) {
            const int nxt = cur ^ 1;
            sm.A[nxt][0][lm * 8 + lq * 2] = nah[0];
            sm.A[nxt][0][lm * 8 + lq * 2 + 1] = nah[1];
            sm.A[nxt][1][lm * 8 + lq * 2] = nal[0];
            sm.A[nxt][1][lm * 8 + lq * 2 + 1] = nal[1];
            ((uint4*)sm.B[nxt][0])[tid] = nwh;
            ((uint4*)sm.B[nxt][1])[tid] = nwl;
            __syncthreads();
        }
    }

    // epilogue: bias, store x, BN stats
    int r0 = m0 + wm * 16 + gr;
    int r1 = r0 + 8;
    bool v0r = (r0 < NN), v1r = (r1 < NN);
#pragma unroll
    for (int nt = 0; nt < 8; nt++) {
        int c0 = wn * 64 + nt * 8 + 2 * kq;
        float bb0 = __ldg(b1 + (size_t)layer * D + c0);
        float bb1 = __ldg(b1 + (size_t)layer * D + c0 + 1);
        float x0 = d[nt][0] + bb0, x1 = d[nt][1] + bb1;
        float x2 = d[nt][2] + bb0, x3 = d[nt][3] + bb1;
        if (v0r) *(float2*)(g_x + (size_t)r0 * D + c0) = make_float2(x0, x1);
        if (v1r) *(float2*)(g_x + (size_t)r1 * D + c0) = make_float2(x2, x3);
        float sc0 = (v0r ? x0 : 0.f) + (v1r ? x2 : 0.f);
        float sc1 = (v0r ? x1 : 0.f) + (v1r ? x3 : 0.f);
        float qc0 = (v0r ? x0 * x0 : 0.f) + (v1r ? x2 * x2 : 0.f);
        float qc1 = (v0r ? x1 * x1 : 0.f) + (v1r ? x3 * x3 : 0.f);
#pragma unroll
        for (int o = 4; o <= 16; o <<= 1) {
            sc0 += __shfl_xor_sync(0xffffffffu, sc0, o);
            sc1 += __shfl_xor_sync(0xffffffffu, sc1, o);
            qc0 += __shfl_xor_sync(0xffffffffu, qc0, o);
            qc1 += __shfl_xor_sync(0xffffffffu, qc1, o);
        }
        if (gr == 0) {
            atomicAdd(&SredS[c0], sc0);
            atomicAdd(&SredS[c0 + 1], sc1);
            atomicAdd(&SredQ[c0], qc0);
            atomicAdd(&SredQ[c0 + 1], qc1);
        }
    }
    __syncthreads();
    if (tid < 128) {
        atomicAdd(&g_stats[layer][tid], SredS[tid]);
        atomicAdd(&g_stats[layer][D + tid], SredQ[tid]);
    }
}

// ---------------- GEMM2: h = relu( relu(BN(x)) @ W2 + b2 ) -> fp16 g_hh ----------------
__global__ void __launch_bounds__(256) gemm2_tc_kernel(const float* __restrict__ b2,
                                                       const float* __restrict__ gamma,
                                                       const float* __restrict__ beta,
                                                       int layer) {
    __shared__ SmemGemm sm;
    __shared__ float s_sc[128], s_sh[128];

    int tid = threadIdx.x;
    int lane = tid & 31;
    int wid = tid >> 5;
    int wm = wid & 3;
    int wn = wid >> 2;
    int m0 = blockIdx.x * 64;

    if (tid < 128) {
        float inv = 1.0f / (float)NN;
        float mu = g_stats[layer][tid] * inv;
        float var = g_stats[layer][D + tid] * inv - mu * mu;
        float rs = rsqrtf(var + 1e-5f);
        float sc = rs * __ldg(gamma + (size_t)layer * D + tid);
        s_sc[tid] = sc;
        s_sh[tid] = __ldg(beta + (size_t)layer * D + tid) - mu * sc;
    }
    __syncthreads();

    int lm = tid >> 2;
    int lq = (tid & 3);
    int gm_ld = m0 + lm;
    const unsigned* Wc = &g_w2p[layer][0][0][0][0];

    // prologue chunk 0: A = relu(BN(x)) split
    {
        float4 v = make_float4(0.f, 0.f, 0.f, 0.f);
        if (gm_ld < NN) {
            float4 xv = *(const float4*)(g_x + (size_t)gm_ld * D + lq * 4);
            int c = lq * 4;
            v.x = fmaxf(fmaf(xv.x, s_sc[c + 0], s_sh[c + 0]), 0.f);
            v.y = fmaxf(fmaf(xv.y, s_sc[c + 1], s_sh[c + 1]), 0.f);
            v.z = fmaxf(fmaf(xv.z, s_sc[c + 2], s_sh[c + 2]), 0.f);
            v.w = fmaxf(fmaf(xv.w, s_sc[c + 3], s_sh[c + 3]), 0.f);
        }
        unsigned hi[2], lo[2];
        split4(v, hi, lo);
        sm.A[0][0][lm * 8 + lq * 2] = hi[0];
        sm.A[0][0][lm * 8 + lq * 2 + 1] = hi[1];
        sm.A[0][1][lm * 8 + lq * 2] = lo[0];
        sm.A[0][1][lm * 8 + lq * 2 + 1] = lo[1];
        const uint4* Wg = (const uint4*)Wc;
        uint4 wh = Wg[tid], wl = Wg[tid + 256];
        ((uint4*)sm.B[0][0])[tid] = wh;
        ((uint4*)sm.B[0][1])[tid] = wl;
    }
    __syncthreads();

    float d[8][4];
#pragma unroll
    for (int nt = 0; nt < 8; nt++)
#pragma unroll
        for (int c = 0; c < 4; c++) d[nt][c] = 0.f;

    int kq = lane & 3;
    int gr = lane >> 2;
    int ca = wm * 16 + gr;

#pragma unroll
    for (int kk = 0; kk < 8; kk++) {
        const int cur = kk & 1;
        unsigned nah[2], nal[2];
        uint4 nwh, nwl;
        if (kk < 7) {
            float4 v = make_float4(0.f, 0.f, 0.f, 0.f);
            int kc = (kk + 1) * 16;
            if (gm_ld < NN) {
                float4 xv = *(const float4*)(g_x + (size_t)gm_ld * D + kc + lq * 4);
                int c = kc + lq * 4;
                v.x = fmaxf(fmaf(xv.x, s_sc[c + 0], s_sh[c + 0]), 0.f);
                v.y = fmaxf(fmaf(xv.y, s_sc[c + 1], s_sh[c + 1]), 0.f);
                v.z = fmaxf(fmaf(xv.z, s_sc[c + 2], s_sh[c + 2]), 0.f);
                v.w = fmaxf(fmaf(xv.w, s_sc[c + 3], s_sh[c + 3]), 0.f);
            }
            split4(v, nah, nal);
            const uint4* Wg = (const uint4*)(Wc + (kk + 1) * 2048);
            nwh = Wg[tid]; nwl = Wg[tid + 256];
        }
        unsigned ah[4], al[4];
        ah[0] = sm.A[cur][0][ca * 8 + kq];
        ah[1] = sm.A[cur][0][(ca + 8) * 8 + kq];
        ah[2] = sm.A[cur][0][ca * 8 + kq + 4];
        ah[3] = sm.A[cur][0][(ca + 8) * 8 + kq + 4];
        al[0] = sm.A[cur][1][ca * 8 + kq];
        al[1] = sm.A[cur][1][(ca + 8) * 8 + kq];
        al[2] = sm.A[cur][1][ca * 8 + kq + 4];
        al[3] = sm.A[cur][1][(ca + 8) * 8 + kq + 4];
#pragma unroll
        for (int nt = 0; nt < 8; nt++) {
            int cb = wn * 64 + nt * 8 + gr;
            unsigned bh0 = sm.B[cur][0][cb * 8 + kq];
            unsigned bh1 = sm.B[cur][0][cb * 8 + kq + 4];
            unsigned bl0 = sm.B[cur][1][cb * 8 + kq];
            unsigned bl1 = sm.B[cur][1][cb * 8 + kq + 4];
            mma_bf16(d[nt], ah, bh0, bh1);
            mma_bf16(d[nt], ah, bl0, bl1);
            mma_bf16(d[nt], al, bh0, bh1);
        }
        if (kk < 7) {
            const int nxt = cur ^ 1;
            sm.A[nxt][0][lm * 8 + lq * 2] = nah[0];
            sm.A[nxt][0][lm * 8 + lq * 2 + 1] = nah[1];
            sm.A[nxt][1][lm * 8 + lq * 2] = nal[0];
            sm.A[nxt][1][lm * 8 + lq * 2 + 1] = nal[1];
            ((uint4*)sm.B[nxt][0])[tid] = nwh;
            ((uint4*)sm.B[nxt][1])[tid] = nwl;
            __syncthreads();
        }
    }

    // epilogue: relu(d + b2) -> g_hh (fp16)
    int r0 = m0 + wm * 16 + gr;
    int r1 = r0 + 8;
#pragma unroll
    for (int nt = 0; nt < 8; nt++) {
        int c0 = wn * 64 + nt * 8 + 2 * kq;
        float bb0 = __ldg(b2 + (size_t)layer * D + c0);
        float bb1 = __ldg(b2 + (size_t)layer * D + c0 + 1);
        if (r0 < NN) {
            *(__half2*)(g_hh + (size_t)r0 * D + c0) =
                __floats2half2_rn(fmaxf(d[nt][0] + bb0, 0.f),
                                  fmaxf(d[nt][1] + bb1, 0.f));
        }
        if (r1 < NN) {
            *(__half2*)(g_hh + (size_t)r1 * D + c0) =
                __floats2half2_rn(fmaxf(d[nt][2] + bb0, 0.f),
                                  fmaxf(d[nt][3] + bb1, 0.f));
        }
    }
}

// ---------------- GEMM3 (fp16 tensor core): out = h @ Wout + bout ----------------
__global__ void __launch_bounds__(256) gemm3_tc_kernel(const float* __restrict__ bout,
                                                       float* __restrict__ out) {
    __shared__ unsigned sA[64 * 8];   // [m][kpair] fp16 pairs
    __shared__ unsigned sB[64 * 8];   // [n][kpair]

    int tid = threadIdx.x;
    int lane = tid & 31;
    int wid = tid >> 5;
    int wm = wid & 3;
    int wn = wid >> 2;
    int m0 = blockIdx.x * 64;

    int lm = tid >> 2;
    int lq = tid & 3;
    int gm_ld = m0 + lm;

    float d[4][4];
#pragma unroll
    for (int nt = 0; nt < 4; nt++)
#pragma unroll
        for (int c = 0; c < 4; c++) d[nt][c] = 0.f;

    int kq = lane & 3;
    int gr = lane >> 2;
    int ca = wm * 16 + gr;

#pragma unroll
    for (int kk = 0; kk < 8; kk++) {
        uint2 a2 = make_uint2(0u, 0u);
        if (gm_ld < NN)
            a2 = *(const uint2*)(g_hh + (size_t)gm_ld * D + kk * 16 + lq * 4);
        sA[lm * 8 + lq * 2] = a2.x;
        sA[lm * 8 + lq * 2 + 1] = a2.y;
        if (tid < 128)
            ((uint4*)sB)[tid] = ((const uint4*)&g_w3p[kk][0][0])[tid];
        __syncthreads();

        unsigned a[4];
        a[0] = sA[ca * 8 + kq];
        a[1] = sA[(ca + 8) * 8 + kq];
        a[2] = sA[ca * 8 + kq + 4];
        a[3] = sA[(ca + 8) * 8 + kq + 4];
#pragma unroll
        for (int nt = 0; nt < 4; nt++) {
            int cb = wn * 32 + nt * 8 + gr;
            unsigned b0 = sB[cb * 8 + kq];
            unsigned b1 = sB[cb * 8 + kq + 4];
            mma_f16(d[nt], a, b0, b1);
        }
        __syncthreads();
    }

    int r0 = m0 + wm * 16 + gr;
    int r1 = r0 + 8;
#pragma unroll
    for (int nt = 0; nt < 4; nt++) {
        int c0 = wn * 32 + nt * 8 + 2 * kq;
        float bb0 = __ldg(bout + c0);
        float bb1 = __ldg(bout + c0 + 1);
        if (r0 < NN)
            *(float2*)(out + (size_t)r0 * OD + c0) =
                make_float2(d[nt][0] + bb0, d[nt][1] + bb1);
        if (r1 < NN)
            *(float2*)(out + (size_t)r1 * OD + c0) =
                make_float2(d[nt][2] + bb0, d[nt][3] + bb1);
    }
}

// ---------------- launch ----------------
extern "C" void kernel_launch(void* const* d_in, const int* in_sizes, int n_in,
                              void* d_out, int out_size) {
    const float* node_feat = (const float*)d_in[0];
    const int*   src       = (const int*)d_in[1];
    const int*   dst       = (const int*)d_in[2];
    const float* W1        = (const float*)d_in[3];
    const float* b1        = (const float*)d_in[4];
    const float* gamma     = (const float*)d_in[5];
    const float* beta      = (const float*)d_in[6];
    const float* W2        = (const float*)d_in[7];
    const float* b2        = (const float*)d_in[8];
    const float* eps       = (const float*)d_in[9];
    const float* Wout      = (const float*)d_in[10];
    const float* bout      = (const float*)d_in[11];
    float* out = (float*)d_out;

    const int gemm_grid  = (NN + 63) / 64;          // 782
    const int edge4_grid = (NE / 4 + 255) / 256;    // 1563
    const int gath_grid  = (NN + 7) / 8;            // 6250
    const int init_grid  = (R_TOT + 255) / 256;

    init_kernel<<<init_grid, 256>>>(node_feat, W1, W2, Wout);
    csr_hist_kernel<<<edge4_grid, 256>>>(dst);
    scan1_kernel<<<NBLK, 256>>>();
    scan2_kernel<<<1, 256>>>();
    scan3_kernel<<<NBLK, 256>>>();
    csr_fill_kernel<<<edge4_grid, 256>>>(src, dst);

    for (int l = 0; l < NL; l++) {
        gather_kernel<<<gath_grid, 256>>>(eps, l);
        gemm1_tc_kernel<<<gemm_grid, 256>>>(b1, l);
        gemm2_tc_kernel<<<gemm_grid, 256>>>(b2, gamma, beta, l);
    }
    gemm3_tc_kernel<<<gemm_grid, 256>>>(bout, out);
}